// round 11
// baseline (speedup 1.0000x reference)
#include <cuda_runtime.h>
#include <cuda_fp16.h>

#define N_NODES 50000
#define N_EDGES 600000
#define HID 128
#define NODE_DIM 64
#define EDGE_DIM 16
#define NLAYERS 3
#define NGRAPHS 256
#define BN_EPS 1e-5f

typedef unsigned long long u64;

// ---------------- scratch (device globals; no allocations allowed) ----------
__device__ __half g_z16[N_NODES * HID];    // node features / pre-BN z, fp16
__device__ __half g_zin16[N_NODES * HID];  // h + agg (MLP input), fp16
__device__ __half g_ea_h[N_EDGES * HID];   // encoded edge features, fp16, CSR order
__device__ __half g_w16[NLAYERS * 2 * HID * HID];  // fp16 MLP weights
__device__ float g_stats[NLAYERS * 2 * HID]; // per-layer column sums / sumsq
__device__ float g_pool[NGRAPHS * HID];    // pooled graph features
// CSR by destination
__device__ int g_cnt[N_NODES];
__device__ int g_off[N_NODES + 1];
__device__ int g_cur[N_NODES];
__device__ int g_csr_src[N_EDGES];
// parallel scan scratch
#define NCHUNK 1024
#define CHSZ ((N_NODES + NCHUNK - 1) / NCHUNK)
__device__ int g_chunk[NCHUNK];
__device__ int g_chunk_base[NCHUNK];

// ---------------- helpers ----------------------------------------------------
__device__ __forceinline__ void red_add_v4(float* p, float4 v) {
    asm volatile("red.global.add.v4.f32 [%0], {%1,%2,%3,%4};"
                 :: "l"(p), "f"(v.x), "f"(v.y), "f"(v.z), "f"(v.w) : "memory");
}

__device__ __forceinline__ float4 h16_load4(const __half* p) {
    uint2 u = *reinterpret_cast<const uint2*>(p);
    __half2 a = *reinterpret_cast<__half2*>(&u.x);
    __half2 b = *reinterpret_cast<__half2*>(&u.y);
    float2 fa = __half22float2(a);
    float2 fb = __half22float2(b);
    return make_float4(fa.x, fa.y, fb.x, fb.y);
}
__device__ __forceinline__ float4 u2_to_f4(uint2 u) {
    __half2 a = *reinterpret_cast<__half2*>(&u.x);
    __half2 b = *reinterpret_cast<__half2*>(&u.y);
    float2 fa = __half22float2(a);
    float2 fb = __half22float2(b);
    return make_float4(fa.x, fa.y, fb.x, fb.y);
}
__device__ __forceinline__ void h16_store4(__half* p, float4 v) {
    union { __half2 h[2]; uint2 u; } cv;
    cv.h[0] = __floats2half2_rn(v.x, v.y);
    cv.h[1] = __floats2half2_rn(v.z, v.w);
    *reinterpret_cast<uint2*>(p) = cv.u;
}

__device__ __forceinline__ unsigned smem_u32(const void* p) {
    return (unsigned)__cvta_generic_to_shared(p);
}
__device__ __forceinline__ void ldsm_x4(unsigned addr, unsigned& r0, unsigned& r1,
                                        unsigned& r2, unsigned& r3) {
    asm volatile("ldmatrix.sync.aligned.m8n8.x4.shared.b16 {%0,%1,%2,%3},[%4];"
                 : "=r"(r0), "=r"(r1), "=r"(r2), "=r"(r3) : "r"(addr));
}
__device__ __forceinline__ void ldsm_x4_t(unsigned addr, unsigned& r0, unsigned& r1,
                                          unsigned& r2, unsigned& r3) {
    asm volatile("ldmatrix.sync.aligned.m8n8.x4.trans.shared.b16 {%0,%1,%2,%3},[%4];"
                 : "=r"(r0), "=r"(r1), "=r"(r2), "=r"(r3) : "r"(addr));
}
__device__ __forceinline__ void mma16816(float& c0, float& c1, float& c2, float& c3,
                                         unsigned a0, unsigned a1, unsigned a2, unsigned a3,
                                         unsigned b0, unsigned b1) {
    asm volatile("mma.sync.aligned.m16n8k16.row.col.f32.f16.f16.f32 "
                 "{%0,%1,%2,%3},{%4,%5,%6,%7},{%8,%9},{%0,%1,%2,%3};"
                 : "+f"(c0), "+f"(c1), "+f"(c2), "+f"(c3)
                 : "r"(a0), "r"(a1), "r"(a2), "r"(a3), "r"(b0), "r"(b1));
}

// ---------------- weight conversion (once) ----------------------------------
__global__ void convert_w_kernel(const float* __restrict__ w1,
                                 const float* __restrict__ w2) {
    int i = blockIdx.x * blockDim.x + threadIdx.x;
    const int per = NLAYERS * HID * HID;
    if (i < per) {
        int l = i / (HID * HID);
        int j = i % (HID * HID);
        g_w16[(size_t)l * 2 * HID * HID + j] = __float2half(w1[i]);
    } else if (i < 2 * per) {
        int k = i - per;
        int l = k / (HID * HID);
        int j = k % (HID * HID);
        g_w16[(size_t)l * 2 * HID * HID + HID * HID + j] = __float2half(w2[k]);
    }
}

// ---------------- node encoder: z16 = x @ node_w + node_b; also zeros -------
__global__ void encoder_kernel(const float* __restrict__ x,
                               const float* __restrict__ W,
                               const float* __restrict__ b) {
    int gt = blockIdx.x * blockDim.x + threadIdx.x;
    int gsz = gridDim.x * blockDim.x;
    for (int i = gt; i < N_NODES; i += gsz) g_cnt[i] = 0;
    for (int i = gt; i < NGRAPHS * HID; i += gsz) g_pool[i] = 0.f;
    for (int i = gt; i < NLAYERS * 2 * HID; i += gsz) g_stats[i] = 0.f;

    __shared__ float sW[NODE_DIM * HID];
    for (int i = threadIdx.x; i < NODE_DIM * HID; i += blockDim.x) sW[i] = W[i];
    __syncthreads();
    int lane = threadIdx.x & 31;
    int warp = gt >> 5;
    int nw = gsz >> 5;
    float4 bb = reinterpret_cast<const float4*>(b)[lane];
    for (int n = warp; n < N_NODES; n += nw) {
        const float4* xr = reinterpret_cast<const float4*>(x + (size_t)n * NODE_DIM);
        float4 acc = bb;
        #pragma unroll
        for (int kk = 0; kk < NODE_DIM / 4; kk++) {
            float4 xv = xr[kk];
            float xa[4] = {xv.x, xv.y, xv.z, xv.w};
            #pragma unroll
            for (int j = 0; j < 4; j++) {
                float4 w = *reinterpret_cast<const float4*>(&sW[(4 * kk + j) * HID + 4 * lane]);
                acc.x += xa[j] * w.x;
                acc.y += xa[j] * w.y;
                acc.z += xa[j] * w.z;
                acc.w += xa[j] * w.w;
            }
        }
        h16_store4(g_z16 + (size_t)n * HID + 4 * lane, acc);
    }
}

// ---------------- CSR build --------------------------------------------------
__global__ void csr_count_kernel(const int* __restrict__ eidx) {
    int e = blockIdx.x * blockDim.x + threadIdx.x;
    if (e < N_EDGES) atomicAdd(&g_cnt[eidx[N_EDGES + e]], 1);
}

__global__ void chunk_sum_kernel() {
    int t = blockIdx.x * blockDim.x + threadIdx.x;
    if (t >= NCHUNK) return;
    int beg = t * CHSZ;
    int end = min(beg + CHSZ, N_NODES);
    int s = 0;
    for (int i = beg; i < end; i++) s += g_cnt[i];
    g_chunk[t] = s;
}

__global__ void chunk_scan_kernel() {
    __shared__ int ssum[NCHUNK];
    int t = threadIdx.x;
    ssum[t] = g_chunk[t];
    __syncthreads();
    for (int off = 1; off < NCHUNK; off <<= 1) {
        int v = (t >= off) ? ssum[t - off] : 0;
        __syncthreads();
        ssum[t] += v;
        __syncthreads();
    }
    g_chunk_base[t] = (t == 0) ? 0 : ssum[t - 1];
    if (t == NCHUNK - 1) g_off[N_NODES] = ssum[t];
}

__global__ void chunk_offs_kernel() {
    int t = blockIdx.x * blockDim.x + threadIdx.x;
    if (t >= NCHUNK) return;
    int beg = t * CHSZ;
    int end = min(beg + CHSZ, N_NODES);
    int run = g_chunk_base[t];
    for (int i = beg; i < end; i++) {
        g_off[i] = run;
        g_cur[i] = run;
        run += g_cnt[i];
    }
}

// --- fused: csr_fill + edge encoder -> fp16 rows in CSR order ---------------
__global__ void edge_enc_fill_kernel(const float* __restrict__ eattr,
                                     const int* __restrict__ eidx,
                                     const float* __restrict__ W,
                                     const float* __restrict__ b) {
    __shared__ float sW[EDGE_DIM * HID];
    __shared__ float sb[HID];
    for (int i = threadIdx.x; i < EDGE_DIM * HID; i += blockDim.x) sW[i] = W[i];
    if (threadIdx.x < HID) sb[threadIdx.x] = b[threadIdx.x];
    __syncthreads();
    int lane = threadIdx.x & 31;
    int warp = (blockIdx.x * blockDim.x + threadIdx.x) >> 5;
    int nw = (gridDim.x * blockDim.x) >> 5;
    float4 bb = reinterpret_cast<const float4*>(sb)[lane];
    for (int e = warp; e < N_EDGES; e += nw) {
        int slot = 0;
        if (lane == 0) {
            int src = eidx[e];
            int dst = eidx[N_EDGES + e];
            slot = atomicAdd(&g_cur[dst], 1);
            g_csr_src[slot] = src;
        }
        slot = __shfl_sync(0xffffffffu, slot, 0);
        const float4* ar = reinterpret_cast<const float4*>(eattr + (size_t)e * EDGE_DIM);
        float4 acc = bb;
        #pragma unroll
        for (int kk = 0; kk < EDGE_DIM / 4; kk++) {
            float4 av = ar[kk];
            float xa[4] = {av.x, av.y, av.z, av.w};
            #pragma unroll
            for (int j = 0; j < 4; j++) {
                float4 w = *reinterpret_cast<const float4*>(&sW[(4 * kk + j) * HID + 4 * lane]);
                acc.x += xa[j] * w.x;
                acc.y += xa[j] * w.y;
                acc.z += xa[j] * w.z;
                acc.w += xa[j] * w.w;
            }
        }
        h16_store4(g_ea_h + (size_t)slot * HID + 4 * lane, acc);
    }
}

// ---- aggregation: 2 nodes per warp, pipelined index prefetch, masked tails --
template<bool BN>
__global__ void agg_kernel(const float* __restrict__ gamma,
                           const float* __restrict__ beta,
                           const float* __restrict__ stats) {
    __shared__ float s_sc[HID], s_sh[HID];
    if (BN) {
        if (threadIdx.x < HID) {
            int c = threadIdx.x;
            const float invN = 1.0f / (float)N_NODES;
            float mean = stats[c] * invN;
            float var = stats[HID + c] * invN - mean * mean;
            float rstd = rsqrtf(var + BN_EPS);
            float sc = gamma[c] * rstd;
            s_sc[c] = sc;
            s_sh[c] = beta[c] - sc * mean;
        }
        __syncthreads();
    }
    int lane = threadIdx.x & 31;
    int warp = (blockIdx.x * blockDim.x + threadIdx.x) >> 5;
    int nw = (gridDim.x * blockDim.x) >> 5;
    float4 sc4 = make_float4(1.f, 1.f, 1.f, 1.f), sh4 = make_float4(0.f, 0.f, 0.f, 0.f);
    if (BN) {
        sc4 = *reinterpret_cast<const float4*>(&s_sc[4 * lane]);
        sh4 = *reinterpret_cast<const float4*>(&s_sh[4 * lane]);
    }
    const __half* zp = g_z16;
    const __half* ep = g_ea_h;
    const int col = 4 * lane;
    const int npairs = N_NODES / 2;   // 25000 (N_NODES even)

    #define BNRELU(v) do { \
        if (BN) { \
            v.x = fmaxf(fmaf(v.x, sc4.x, sh4.x), 0.f); \
            v.y = fmaxf(fmaf(v.y, sc4.y, sh4.y), 0.f); \
            v.z = fmaxf(fmaf(v.z, sc4.z, sh4.z), 0.f); \
            v.w = fmaxf(fmaf(v.w, sc4.w, sh4.w), 0.f); \
        } } while (0)

    for (int p = warp; p < npairs; p += nw) {
        int nA = 2 * p, nB = 2 * p + 1;
        float4 accA = u2_to_f4(*reinterpret_cast<const uint2*>(zp + (size_t)nA * HID + col));
        float4 accB = u2_to_f4(*reinterpret_cast<const uint2*>(zp + (size_t)nB * HID + col));
        BNRELU(accA);
        BNRELU(accB);

        int ia = __ldg(&g_off[nA]);
        int eA = __ldg(&g_off[nA + 1]);
        int ib = eA;                       // off[nB] == off[nA+1]
        int eB = __ldg(&g_off[nB + 1]);
        int steps = (max(eA - ia, eB - ib) + 1) >> 1;

        // prefetch first iteration's slots + src ids
        int ca0 = max(min(ia, eA - 1), 0), ca1 = max(min(ia + 1, eA - 1), 0);
        int cb0 = max(min(ib, eB - 1), 0), cb1 = max(min(ib + 1, eB - 1), 0);
        int ja0 = __ldg(&g_csr_src[ca0]), ja1 = __ldg(&g_csr_src[ca1]);
        int jb0 = __ldg(&g_csr_src[cb0]), jb1 = __ldg(&g_csr_src[cb1]);

        for (int s = 0; s < steps; s++) {
            float ma0 = (ia < eA) ? 1.f : 0.f;
            float ma1 = (ia + 1 < eA) ? 1.f : 0.f;
            float mb0 = (ib < eB) ? 1.f : 0.f;
            float mb1 = (ib + 1 < eB) ? 1.f : 0.f;
            int sa0 = ja0, sa1 = ja1, sb0 = jb0, sb1 = jb1;
            int ea0 = ca0, ea1 = ca1, eb0 = cb0, eb1 = cb1;
            ia += 2; ib += 2;
            // prefetch next iteration (indices ready before gathers land)
            ca0 = max(min(ia, eA - 1), 0); ca1 = max(min(ia + 1, eA - 1), 0);
            cb0 = max(min(ib, eB - 1), 0); cb1 = max(min(ib + 1, eB - 1), 0);
            ja0 = __ldg(&g_csr_src[ca0]); ja1 = __ldg(&g_csr_src[ca1]);
            jb0 = __ldg(&g_csr_src[cb0]); jb1 = __ldg(&g_csr_src[cb1]);
            // 8 independent loads in flight
            uint2 HA0 = *reinterpret_cast<const uint2*>(zp + (size_t)sa0 * HID + col);
            uint2 HA1 = *reinterpret_cast<const uint2*>(zp + (size_t)sa1 * HID + col);
            uint2 HB0 = *reinterpret_cast<const uint2*>(zp + (size_t)sb0 * HID + col);
            uint2 HB1 = *reinterpret_cast<const uint2*>(zp + (size_t)sb1 * HID + col);
            uint2 EA0 = *reinterpret_cast<const uint2*>(ep + (size_t)ea0 * HID + col);
            uint2 EA1 = *reinterpret_cast<const uint2*>(ep + (size_t)ea1 * HID + col);
            uint2 EB0 = *reinterpret_cast<const uint2*>(ep + (size_t)eb0 * HID + col);
            uint2 EB1 = *reinterpret_cast<const uint2*>(ep + (size_t)eb1 * HID + col);

            float4 h0 = u2_to_f4(HA0), h1 = u2_to_f4(HA1);
            float4 h2 = u2_to_f4(HB0), h3 = u2_to_f4(HB1);
            float4 e0 = u2_to_f4(EA0), e1 = u2_to_f4(EA1);
            float4 e2 = u2_to_f4(EB0), e3 = u2_to_f4(EB1);
            BNRELU(h0); BNRELU(h1); BNRELU(h2); BNRELU(h3);

            accA.x = fmaf(ma0, fmaxf(h0.x + e0.x, 0.f), accA.x);
            accA.y = fmaf(ma0, fmaxf(h0.y + e0.y, 0.f), accA.y);
            accA.z = fmaf(ma0, fmaxf(h0.z + e0.z, 0.f), accA.z);
            accA.w = fmaf(ma0, fmaxf(h0.w + e0.w, 0.f), accA.w);
            accA.x = fmaf(ma1, fmaxf(h1.x + e1.x, 0.f), accA.x);
            accA.y = fmaf(ma1, fmaxf(h1.y + e1.y, 0.f), accA.y);
            accA.z = fmaf(ma1, fmaxf(h1.z + e1.z, 0.f), accA.z);
            accA.w = fmaf(ma1, fmaxf(h1.w + e1.w, 0.f), accA.w);
            accB.x = fmaf(mb0, fmaxf(h2.x + e2.x, 0.f), accB.x);
            accB.y = fmaf(mb0, fmaxf(h2.y + e2.y, 0.f), accB.y);
            accB.z = fmaf(mb0, fmaxf(h2.z + e2.z, 0.f), accB.z);
            accB.w = fmaf(mb0, fmaxf(h2.w + e2.w, 0.f), accB.w);
            accB.x = fmaf(mb1, fmaxf(h3.x + e3.x, 0.f), accB.x);
            accB.y = fmaf(mb1, fmaxf(h3.y + e3.y, 0.f), accB.y);
            accB.z = fmaf(mb1, fmaxf(h3.z + e3.z, 0.f), accB.z);
            accB.w = fmaf(mb1, fmaxf(h3.w + e3.w, 0.f), accB.w);
        }
        h16_store4(g_zin16 + (size_t)nA * HID + col, accA);
        h16_store4(g_zin16 + (size_t)nB * HID + col, accB);
    }
    #undef BNRELU
}

// ---------------- MLP via tensor cores (mma.sync m16n8k16) ------------------
#define LDT 136
#define MLP_SMEM_BYTES (4 * HID * LDT * 2 + 2 * HID * 4)
__global__ __launch_bounds__(512, 1)
void mlp_mma_kernel(const __half* __restrict__ W16,
                    const float* __restrict__ B1, const float* __restrict__ B2,
                    float* __restrict__ stats) {
    extern __shared__ __half smh[];
    __half* sW1 = smh;
    __half* sW2 = sW1 + HID * LDT;
    __half* sIn = sW2 + HID * LDT;
    __half* sT  = sIn + HID * LDT;
    float* sB1 = (float*)(sT + HID * LDT);
    float* sB2 = sB1 + HID;

    int tid = threadIdx.x;
    int lane = tid & 31;
    int wid = tid >> 5;
    int wr = wid >> 2;
    int wc = wid & 3;

    for (int i = tid; i < HID * HID; i += 512) {
        int r = i >> 7, c = i & 127;
        sW1[r * LDT + c] = W16[i];
        sW2[r * LDT + c] = W16[HID * HID + i];
    }
    if (tid < HID) { sB1[tid] = B1[tid]; sB2[tid] = B2[tid]; }
    __syncthreads();

    int rpb = (N_NODES + gridDim.x - 1) / gridDim.x;
    int base = blockIdx.x * rpb;
    int rend = min(base + rpb, N_NODES);

    float ls[8], lss[8];
    #pragma unroll
    for (int j = 0; j < 8; j++) { ls[j] = 0.f; lss[j] = 0.f; }

    const int qlane = lane & 3;
    const int rlane = lane >> 2;

    for (int rbase = base; rbase < rend; rbase += HID) {
        for (int i = tid; i < HID * 16; i += 512) {
            int r = i >> 4, q = i & 15;
            int row = rbase + r;
            uint4 v = make_uint4(0u, 0u, 0u, 0u);
            if (row < rend) v = *reinterpret_cast<const uint4*>(g_zin16 + (size_t)row * HID + q * 8);
            *reinterpret_cast<uint4*>(&sIn[r * LDT + q * 8]) = v;
        }
        __syncthreads();

        float acc[2][4][4];
        #pragma unroll
        for (int mb = 0; mb < 2; mb++)
            #pragma unroll
            for (int nb = 0; nb < 4; nb++)
                #pragma unroll
                for (int j = 0; j < 4; j++) acc[mb][nb][j] = 0.f;

        #pragma unroll
        for (int ks = 0; ks < 8; ks++) {
            int k0 = ks * 16;
            unsigned a[2][4];
            #pragma unroll
            for (int mb = 0; mb < 2; mb++) {
                int row = wr * 32 + mb * 16 + (lane & 15);
                unsigned addr = smem_u32(&sIn[row * LDT + k0 + ((lane >> 4) << 3)]);
                ldsm_x4(addr, a[mb][0], a[mb][1], a[mb][2], a[mb][3]);
            }
            unsigned b[4][2];
            #pragma unroll
            for (int np = 0; np < 2; np++) {
                int krow = k0 + (lane & 15);
                int n0 = wc * 32 + np * 16 + ((lane >> 4) << 3);
                unsigned addr = smem_u32(&sW1[krow * LDT + n0]);
                unsigned r0, r1, r2, r3;
                ldsm_x4_t(addr, r0, r1, r2, r3);
                b[2 * np][0] = r0; b[2 * np][1] = r1;
                b[2 * np + 1][0] = r2; b[2 * np + 1][1] = r3;
            }
            #pragma unroll
            for (int mb = 0; mb < 2; mb++)
                #pragma unroll
                for (int nb = 0; nb < 4; nb++)
                    mma16816(acc[mb][nb][0], acc[mb][nb][1], acc[mb][nb][2], acc[mb][nb][3],
                             a[mb][0], a[mb][1], a[mb][2], a[mb][3], b[nb][0], b[nb][1]);
        }
        __syncthreads();
        #pragma unroll
        for (int mb = 0; mb < 2; mb++) {
            #pragma unroll
            for (int nb = 0; nb < 4; nb++) {
                int col = wc * 32 + nb * 8 + 2 * qlane;
                float bx = sB1[col], by = sB1[col + 1];
                int rlo = wr * 32 + mb * 16 + rlane;
                *reinterpret_cast<__half2*>(&sT[rlo * LDT + col]) =
                    __floats2half2_rn(fmaxf(acc[mb][nb][0] + bx, 0.f),
                                      fmaxf(acc[mb][nb][1] + by, 0.f));
                *reinterpret_cast<__half2*>(&sT[(rlo + 8) * LDT + col]) =
                    __floats2half2_rn(fmaxf(acc[mb][nb][2] + bx, 0.f),
                                      fmaxf(acc[mb][nb][3] + by, 0.f));
            }
        }
        __syncthreads();

        #pragma unroll
        for (int mb = 0; mb < 2; mb++)
            #pragma unroll
            for (int nb = 0; nb < 4; nb++)
                #pragma unroll
                for (int j = 0; j < 4; j++) acc[mb][nb][j] = 0.f;

        #pragma unroll
        for (int ks = 0; ks < 8; ks++) {
            int k0 = ks * 16;
            unsigned a[2][4];
            #pragma unroll
            for (int mb = 0; mb < 2; mb++) {
                int row = wr * 32 + mb * 16 + (lane & 15);
                unsigned addr = smem_u32(&sT[row * LDT + k0 + ((lane >> 4) << 3)]);
                ldsm_x4(addr, a[mb][0], a[mb][1], a[mb][2], a[mb][3]);
            }
            unsigned b[4][2];
            #pragma unroll
            for (int np = 0; np < 2; np++) {
                int krow = k0 + (lane & 15);
                int n0 = wc * 32 + np * 16 + ((lane >> 4) << 3);
                unsigned addr = smem_u32(&sW2[krow * LDT + n0]);
                unsigned r0, r1, r2, r3;
                ldsm_x4_t(addr, r0, r1, r2, r3);
                b[2 * np][0] = r0; b[2 * np][1] = r1;
                b[2 * np + 1][0] = r2; b[2 * np + 1][1] = r3;
            }
            #pragma unroll
            for (int mb = 0; mb < 2; mb++)
                #pragma unroll
                for (int nb = 0; nb < 4; nb++)
                    mma16816(acc[mb][nb][0], acc[mb][nb][1], acc[mb][nb][2], acc[mb][nb][3],
                             a[mb][0], a[mb][1], a[mb][2], a[mb][3], b[nb][0], b[nb][1]);
        }
        #pragma unroll
        for (int mb = 0; mb < 2; mb++) {
            #pragma unroll
            for (int nb = 0; nb < 4; nb++) {
                int col = wc * 32 + nb * 8 + 2 * qlane;
                float bx = sB2[col], by = sB2[col + 1];
                int rlo = rbase + wr * 32 + mb * 16 + rlane;
                float z0 = acc[mb][nb][0] + bx, z1 = acc[mb][nb][1] + by;
                float z2 = acc[mb][nb][2] + bx, z3 = acc[mb][nb][3] + by;
                if (rlo < rend) {
                    *reinterpret_cast<__half2*>(&g_z16[(size_t)rlo * HID + col]) =
                        __floats2half2_rn(z0, z1);
                    ls[2 * nb] += z0; lss[2 * nb] += z0 * z0;
                    ls[2 * nb + 1] += z1; lss[2 * nb + 1] += z1 * z1;
                }
                if (rlo + 8 < rend) {
                    *reinterpret_cast<__half2*>(&g_z16[(size_t)(rlo + 8) * HID + col]) =
                        __floats2half2_rn(z2, z3);
                    ls[2 * nb] += z2; lss[2 * nb] += z2 * z2;
                    ls[2 * nb + 1] += z3; lss[2 * nb + 1] += z3 * z3;
                }
            }
        }
        __syncthreads();
    }

    #pragma unroll
    for (int j = 0; j < 8; j++) {
        #pragma unroll
        for (int o = 4; o < 32; o <<= 1) {
            ls[j]  += __shfl_xor_sync(0xffffffffu, ls[j], o);
            lss[j] += __shfl_xor_sync(0xffffffffu, lss[j], o);
        }
    }
    if (lane < 4) {
        #pragma unroll
        for (int nb = 0; nb < 4; nb++) {
            #pragma unroll
            for (int j = 0; j < 2; j++) {
                int col = wc * 32 + nb * 8 + 2 * lane + j;
                atomicAdd(&stats[col], ls[2 * nb + j]);
                atomicAdd(&stats[HID + col], lss[2 * nb + j]);
            }
        }
    }
}

// ---------------- last layer: BN + relu + pool (reads z16) ------------------
__global__ void bn_pool_kernel(const float* __restrict__ gamma,
                               const float* __restrict__ beta,
                               const float* __restrict__ stats,
                               const int* __restrict__ batch) {
    int i = blockIdx.x * blockDim.x + threadIdx.x;
    const int n4 = N_NODES * HID / 4;
    if (i >= n4) return;
    int n = i >> 5;
    int c0 = (i & 31) * 4;
    float4 z = h16_load4(g_z16 + (size_t)i * 4);
    float za[4] = {z.x, z.y, z.z, z.w};
    float out[4];
    const float invN = 1.0f / (float)N_NODES;
    #pragma unroll
    for (int j = 0; j < 4; j++) {
        int c = c0 + j;
        float mean = stats[c] * invN;
        float var = stats[HID + c] * invN - mean * mean;
        float rstd = rsqrtf(var + BN_EPS);
        float o = gamma[c] * (za[j] - mean) * rstd + beta[c];
        out[j] = fmaxf(o, 0.f);
    }
    int gi = __ldg(&batch[n]);
    red_add_v4(g_pool + (size_t)gi * HID + c0,
               make_float4(out[0], out[1], out[2], out[3]));
}

// ---------------- head: out = relu(g@W1+b1)@W2+b2 ---------------------------
__global__ void head_kernel(const float* __restrict__ w1, const float* __restrict__ b1,
                            const float* __restrict__ w2, const float* __restrict__ b2,
                            float* __restrict__ out) {
    __shared__ float srow[HID];
    __shared__ float st[HID];
    int gi = blockIdx.x;
    int c = threadIdx.x;
    srow[c] = g_pool[(size_t)gi * HID + c];
    __syncthreads();
    float acc = b1[c];
    for (int k = 0; k < HID; k++) acc += srow[k] * w1[k * HID + c];
    st[c] = fmaxf(acc, 0.f);
    __syncthreads();
    if (c < 2) {
        float o = b2[c];
        for (int k = 0; k < HID; k++) o += st[k] * w2[k * 2 + c];
        out[gi * 2 + c] = o;
    }
}

// ---------------- launch -----------------------------------------------------
extern "C" void kernel_launch(void* const* d_in, const int* in_sizes, int n_in,
                              void* d_out, int out_size) {
    const float* x        = (const float*)d_in[0];
    const int*   eidx     = (const int*)d_in[1];
    const float* eattr    = (const float*)d_in[2];
    const int*   batch    = (const int*)d_in[3];
    const float* node_w   = (const float*)d_in[4];
    const float* node_b   = (const float*)d_in[5];
    const float* edge_w   = (const float*)d_in[6];
    const float* edge_b   = (const float*)d_in[7];
    const float* mlp_w1   = (const float*)d_in[8];
    const float* mlp_b1   = (const float*)d_in[9];
    const float* mlp_w2   = (const float*)d_in[10];
    const float* mlp_b2   = (const float*)d_in[11];
    const float* bn_gamma = (const float*)d_in[12];
    const float* bn_beta  = (const float*)d_in[13];
    const float* head_w1  = (const float*)d_in[14];
    const float* head_b1  = (const float*)d_in[15];
    const float* head_w2  = (const float*)d_in[16];
    const float* head_b2  = (const float*)d_in[17];
    float* out = (float*)d_out;

    cudaFuncSetAttribute(mlp_mma_kernel, cudaFuncAttributeMaxDynamicSharedMemorySize,
                         MLP_SMEM_BYTES);

    float* d_stats;
    cudaGetSymbolAddress((void**)&d_stats, g_stats);
    __half* d_w16;
    cudaGetSymbolAddress((void**)&d_w16, g_w16);

    convert_w_kernel<<<(2 * NLAYERS * HID * HID + 255) / 256, 256>>>(mlp_w1, mlp_w2);
    encoder_kernel<<<512, 256>>>(x, node_w, node_b);

    csr_count_kernel<<<(N_EDGES + 255) / 256, 256>>>(eidx);
    chunk_sum_kernel<<<NCHUNK / 128, 128>>>();
    chunk_scan_kernel<<<1, NCHUNK>>>();
    chunk_offs_kernel<<<NCHUNK / 128, 128>>>();
    edge_enc_fill_kernel<<<2048, 256>>>(eattr, eidx, edge_w, edge_b);

    for (int l = 0; l < NLAYERS; l++) {
        if (l == 0) {
            agg_kernel<false><<<1024, 256>>>(nullptr, nullptr, nullptr);
        } else {
            agg_kernel<true><<<1024, 256>>>(bn_gamma + (size_t)(l - 1) * HID,
                                            bn_beta + (size_t)(l - 1) * HID,
                                            d_stats + (size_t)(l - 1) * 2 * HID);
        }
        mlp_mma_kernel<<<148, 512, MLP_SMEM_BYTES>>>(
            d_w16 + (size_t)l * 2 * HID * HID,
            mlp_b1 + (size_t)l * HID,
            mlp_b2 + (size_t)l * HID,
            d_stats + (size_t)l * 2 * HID);
    }

    bn_pool_kernel<<<(N_NODES * HID / 4 + 255) / 256, 256>>>(
        bn_gamma + (size_t)(NLAYERS - 1) * HID,
        bn_beta + (size_t)(NLAYERS - 1) * HID,
        d_stats + (size_t)(NLAYERS - 1) * 2 * HID, batch);
    head_kernel<<<NGRAPHS, HID>>>(head_w1, head_b1, head_w2, head_b2, out);
}

// round 12
// speedup vs baseline: 1.1150x; 1.1150x over previous
#include <cuda_runtime.h>
#include <cuda_fp16.h>

#define N_NODES 50000
#define N_EDGES 600000
#define HID 128
#define NODE_DIM 64
#define EDGE_DIM 16
#define NLAYERS 3
#define NGRAPHS 256
#define BN_EPS 1e-5f

typedef unsigned long long u64;

// ---------------- scratch (device globals; no allocations allowed) ----------
__device__ __half g_z16[N_NODES * HID];    // node features / pre-BN z, fp16
__device__ __half g_zin16[N_NODES * HID];  // h + agg (MLP input), fp16
__device__ __half g_ea_h[N_EDGES * HID];   // encoded edge features, fp16, CSR order
__device__ __half g_w16[NLAYERS * 2 * HID * HID];  // fp16 MLP weights
__device__ float g_stats[NLAYERS * 2 * HID]; // per-layer column sums / sumsq
__device__ float g_pool[NGRAPHS * HID];    // pooled graph features
// CSR by destination
__device__ int g_cnt[N_NODES];
__device__ int g_off[N_NODES + 1];
__device__ int g_cur[N_NODES];
__device__ int g_csr_src[N_EDGES];
// parallel scan scratch
#define NCHUNK 1024
#define CHSZ ((N_NODES + NCHUNK - 1) / NCHUNK)
__device__ int g_chunk[NCHUNK];
__device__ int g_chunk_base[NCHUNK];

// ---------------- helpers ----------------------------------------------------
__device__ __forceinline__ void red_add_v4(float* p, float4 v) {
    asm volatile("red.global.add.v4.f32 [%0], {%1,%2,%3,%4};"
                 :: "l"(p), "f"(v.x), "f"(v.y), "f"(v.z), "f"(v.w) : "memory");
}

__device__ __forceinline__ float4 h16_load4(const __half* p) {
    uint2 u = *reinterpret_cast<const uint2*>(p);
    __half2 a = *reinterpret_cast<__half2*>(&u.x);
    __half2 b = *reinterpret_cast<__half2*>(&u.y);
    float2 fa = __half22float2(a);
    float2 fb = __half22float2(b);
    return make_float4(fa.x, fa.y, fb.x, fb.y);
}
__device__ __forceinline__ void h16_store4(__half* p, float4 v) {
    union { __half2 h[2]; uint2 u; } cv;
    cv.h[0] = __floats2half2_rn(v.x, v.y);
    cv.h[1] = __floats2half2_rn(v.z, v.w);
    *reinterpret_cast<uint2*>(p) = cv.u;
}

__device__ __forceinline__ unsigned smem_u32(const void* p) {
    return (unsigned)__cvta_generic_to_shared(p);
}
__device__ __forceinline__ void ldsm_x4(unsigned addr, unsigned& r0, unsigned& r1,
                                        unsigned& r2, unsigned& r3) {
    asm volatile("ldmatrix.sync.aligned.m8n8.x4.shared.b16 {%0,%1,%2,%3},[%4];"
                 : "=r"(r0), "=r"(r1), "=r"(r2), "=r"(r3) : "r"(addr));
}
__device__ __forceinline__ void ldsm_x4_t(unsigned addr, unsigned& r0, unsigned& r1,
                                          unsigned& r2, unsigned& r3) {
    asm volatile("ldmatrix.sync.aligned.m8n8.x4.trans.shared.b16 {%0,%1,%2,%3},[%4];"
                 : "=r"(r0), "=r"(r1), "=r"(r2), "=r"(r3) : "r"(addr));
}
__device__ __forceinline__ void mma16816(float& c0, float& c1, float& c2, float& c3,
                                         unsigned a0, unsigned a1, unsigned a2, unsigned a3,
                                         unsigned b0, unsigned b1) {
    asm volatile("mma.sync.aligned.m16n8k16.row.col.f32.f16.f16.f32 "
                 "{%0,%1,%2,%3},{%4,%5,%6,%7},{%8,%9},{%0,%1,%2,%3};"
                 : "+f"(c0), "+f"(c1), "+f"(c2), "+f"(c3)
                 : "r"(a0), "r"(a1), "r"(a2), "r"(a3), "r"(b0), "r"(b1));
}

// ---------------- weight conversion + zeroing (launch 0) --------------------
__global__ void convert_w_kernel(const float* __restrict__ w1,
                                 const float* __restrict__ w2) {
    int gt = blockIdx.x * blockDim.x + threadIdx.x;
    int gsz = gridDim.x * blockDim.x;
    for (int i = gt; i < N_NODES; i += gsz) g_cnt[i] = 0;
    for (int i = gt; i < NGRAPHS * HID; i += gsz) g_pool[i] = 0.f;
    for (int i = gt; i < NLAYERS * 2 * HID; i += gsz) g_stats[i] = 0.f;

    int i = gt;
    const int per = NLAYERS * HID * HID;
    if (i < per) {
        int l = i / (HID * HID);
        int j = i % (HID * HID);
        g_w16[(size_t)l * 2 * HID * HID + j] = __float2half(w1[i]);
    } else if (i < 2 * per) {
        int k = i - per;
        int l = k / (HID * HID);
        int j = k % (HID * HID);
        g_w16[(size_t)l * 2 * HID * HID + HID * HID + j] = __float2half(w2[k]);
    }
}

// ---------------- CSR build --------------------------------------------------
__global__ void csr_count_kernel(const int* __restrict__ eidx) {
    int e = blockIdx.x * blockDim.x + threadIdx.x;
    if (e < N_EDGES) atomicAdd(&g_cnt[eidx[N_EDGES + e]], 1);
}

__global__ void chunk_sum_kernel() {
    int t = blockIdx.x * blockDim.x + threadIdx.x;
    if (t >= NCHUNK) return;
    int beg = t * CHSZ;
    int end = min(beg + CHSZ, N_NODES);
    int s = 0;
    for (int i = beg; i < end; i++) s += g_cnt[i];
    g_chunk[t] = s;
}

__global__ void chunk_scan_kernel() {
    __shared__ int ssum[NCHUNK];
    int t = threadIdx.x;
    ssum[t] = g_chunk[t];
    __syncthreads();
    for (int off = 1; off < NCHUNK; off <<= 1) {
        int v = (t >= off) ? ssum[t - off] : 0;
        __syncthreads();
        ssum[t] += v;
        __syncthreads();
    }
    g_chunk_base[t] = (t == 0) ? 0 : ssum[t - 1];
    if (t == NCHUNK - 1) g_off[N_NODES] = ssum[t];
}

__global__ void chunk_offs_kernel() {
    int t = blockIdx.x * blockDim.x + threadIdx.x;
    if (t >= NCHUNK) return;
    int beg = t * CHSZ;
    int end = min(beg + CHSZ, N_NODES);
    int run = g_chunk_base[t];
    for (int i = beg; i < end; i++) {
        g_off[i] = run;
        g_cur[i] = run;
        run += g_cnt[i];
    }
}

// --- fused: csr_fill + edge encoder -> fp16 rows in CSR order ---------------
__global__ void edge_enc_fill_kernel(const float* __restrict__ eattr,
                                     const int* __restrict__ eidx,
                                     const float* __restrict__ W,
                                     const float* __restrict__ b) {
    __shared__ float sW[EDGE_DIM * HID];
    __shared__ float sb[HID];
    for (int i = threadIdx.x; i < EDGE_DIM * HID; i += blockDim.x) sW[i] = W[i];
    if (threadIdx.x < HID) sb[threadIdx.x] = b[threadIdx.x];
    __syncthreads();
    int lane = threadIdx.x & 31;
    int warp = (blockIdx.x * blockDim.x + threadIdx.x) >> 5;
    int nw = (gridDim.x * blockDim.x) >> 5;
    float4 bb = reinterpret_cast<const float4*>(sb)[lane];
    for (int e = warp; e < N_EDGES; e += nw) {
        int slot = 0;
        if (lane == 0) {
            int src = eidx[e];
            int dst = eidx[N_EDGES + e];
            slot = atomicAdd(&g_cur[dst], 1);
            g_csr_src[slot] = src;
        }
        slot = __shfl_sync(0xffffffffu, slot, 0);
        const float4* ar = reinterpret_cast<const float4*>(eattr + (size_t)e * EDGE_DIM);
        float4 acc = bb;
        #pragma unroll
        for (int kk = 0; kk < EDGE_DIM / 4; kk++) {
            float4 av = ar[kk];
            float xa[4] = {av.x, av.y, av.z, av.w};
            #pragma unroll
            for (int j = 0; j < 4; j++) {
                float4 w = *reinterpret_cast<const float4*>(&sW[(4 * kk + j) * HID + 4 * lane]);
                acc.x += xa[j] * w.x;
                acc.y += xa[j] * w.y;
                acc.z += xa[j] * w.z;
                acc.w += xa[j] * w.w;
            }
        }
        h16_store4(g_ea_h + (size_t)slot * HID + 4 * lane, acc);
    }
}

// ---------------- node encoder: z16 = x @ node_w + node_b -------------------
__global__ void encoder_kernel(const float* __restrict__ x,
                               const float* __restrict__ W,
                               const float* __restrict__ b) {
    __shared__ float sW[NODE_DIM * HID];
    for (int i = threadIdx.x; i < NODE_DIM * HID; i += blockDim.x) sW[i] = W[i];
    __syncthreads();
    int lane = threadIdx.x & 31;
    int warp = (blockIdx.x * blockDim.x + threadIdx.x) >> 5;
    int nw = (gridDim.x * blockDim.x) >> 5;
    float4 bb = reinterpret_cast<const float4*>(b)[lane];
    for (int n = warp; n < N_NODES; n += nw) {
        const float4* xr = reinterpret_cast<const float4*>(x + (size_t)n * NODE_DIM);
        float4 acc = bb;
        #pragma unroll
        for (int kk = 0; kk < NODE_DIM / 4; kk++) {
            float4 xv = xr[kk];
            float xa[4] = {xv.x, xv.y, xv.z, xv.w};
            #pragma unroll
            for (int j = 0; j < 4; j++) {
                float4 w = *reinterpret_cast<const float4*>(&sW[(4 * kk + j) * HID + 4 * lane]);
                acc.x += xa[j] * w.x;
                acc.y += xa[j] * w.y;
                acc.z += xa[j] * w.z;
                acc.w += xa[j] * w.w;
            }
        }
        h16_store4(g_z16 + (size_t)n * HID + 4 * lane, acc);
    }
}

// ---- aggregation with inline BN of previous layer; x4/x2/x1 cascade --------
template<bool BN>
__global__ void agg_kernel(const float* __restrict__ gamma,
                           const float* __restrict__ beta,
                           const float* __restrict__ stats) {
    __shared__ float s_sc[HID], s_sh[HID];
    if (BN) {
        if (threadIdx.x < HID) {
            int c = threadIdx.x;
            const float invN = 1.0f / (float)N_NODES;
            float mean = stats[c] * invN;
            float var = stats[HID + c] * invN - mean * mean;
            float rstd = rsqrtf(var + BN_EPS);
            float sc = gamma[c] * rstd;
            s_sc[c] = sc;
            s_sh[c] = beta[c] - sc * mean;
        }
        __syncthreads();
    }
    int lane = threadIdx.x & 31;
    int warp = (blockIdx.x * blockDim.x + threadIdx.x) >> 5;
    int nw = (gridDim.x * blockDim.x) >> 5;
    float4 sc4 = make_float4(1.f, 1.f, 1.f, 1.f), sh4 = make_float4(0.f, 0.f, 0.f, 0.f);
    if (BN) {
        sc4 = *reinterpret_cast<const float4*>(&s_sc[4 * lane]);
        sh4 = *reinterpret_cast<const float4*>(&s_sh[4 * lane]);
    }

    const __half* zp = g_z16;
    const __half* ep = g_ea_h;

    #define BNRELU(v) do { \
        if (BN) { \
            v.x = fmaxf(fmaf(v.x, sc4.x, sh4.x), 0.f); \
            v.y = fmaxf(fmaf(v.y, sc4.y, sh4.y), 0.f); \
            v.z = fmaxf(fmaf(v.z, sc4.z, sh4.z), 0.f); \
            v.w = fmaxf(fmaf(v.w, sc4.w, sh4.w), 0.f); \
        } } while (0)

    for (int n = warp; n < N_NODES; n += nw) {
        float4 acc = h16_load4(zp + (size_t)n * HID + 4 * lane);
        BNRELU(acc);
        int s = __ldg(&g_off[n]);
        int e = __ldg(&g_off[n + 1]);
        int idx = s;
        for (; idx + 4 <= e; idx += 4) {
            int s0 = __ldg(&g_csr_src[idx]);
            int s1 = __ldg(&g_csr_src[idx + 1]);
            int s2 = __ldg(&g_csr_src[idx + 2]);
            int s3 = __ldg(&g_csr_src[idx + 3]);
            float4 h0 = h16_load4(zp + (size_t)s0 * HID + 4 * lane);
            float4 h1 = h16_load4(zp + (size_t)s1 * HID + 4 * lane);
            float4 h2 = h16_load4(zp + (size_t)s2 * HID + 4 * lane);
            float4 h3 = h16_load4(zp + (size_t)s3 * HID + 4 * lane);
            float4 e0 = h16_load4(ep + (size_t)(idx + 0) * HID + 4 * lane);
            float4 e1 = h16_load4(ep + (size_t)(idx + 1) * HID + 4 * lane);
            float4 e2 = h16_load4(ep + (size_t)(idx + 2) * HID + 4 * lane);
            float4 e3 = h16_load4(ep + (size_t)(idx + 3) * HID + 4 * lane);
            BNRELU(h0); BNRELU(h1); BNRELU(h2); BNRELU(h3);
            acc.x += fmaxf(h0.x + e0.x, 0.f) + fmaxf(h1.x + e1.x, 0.f)
                   + fmaxf(h2.x + e2.x, 0.f) + fmaxf(h3.x + e3.x, 0.f);
            acc.y += fmaxf(h0.y + e0.y, 0.f) + fmaxf(h1.y + e1.y, 0.f)
                   + fmaxf(h2.y + e2.y, 0.f) + fmaxf(h3.y + e3.y, 0.f);
            acc.z += fmaxf(h0.z + e0.z, 0.f) + fmaxf(h1.z + e1.z, 0.f)
                   + fmaxf(h2.z + e2.z, 0.f) + fmaxf(h3.z + e3.z, 0.f);
            acc.w += fmaxf(h0.w + e0.w, 0.f) + fmaxf(h1.w + e1.w, 0.f)
                   + fmaxf(h2.w + e2.w, 0.f) + fmaxf(h3.w + e3.w, 0.f);
        }
        if (idx + 2 <= e) {
            int s0 = __ldg(&g_csr_src[idx]);
            int s1 = __ldg(&g_csr_src[idx + 1]);
            float4 h0 = h16_load4(zp + (size_t)s0 * HID + 4 * lane);
            float4 h1 = h16_load4(zp + (size_t)s1 * HID + 4 * lane);
            float4 e0 = h16_load4(ep + (size_t)(idx + 0) * HID + 4 * lane);
            float4 e1 = h16_load4(ep + (size_t)(idx + 1) * HID + 4 * lane);
            BNRELU(h0); BNRELU(h1);
            acc.x += fmaxf(h0.x + e0.x, 0.f) + fmaxf(h1.x + e1.x, 0.f);
            acc.y += fmaxf(h0.y + e0.y, 0.f) + fmaxf(h1.y + e1.y, 0.f);
            acc.z += fmaxf(h0.z + e0.z, 0.f) + fmaxf(h1.z + e1.z, 0.f);
            acc.w += fmaxf(h0.w + e0.w, 0.f) + fmaxf(h1.w + e1.w, 0.f);
            idx += 2;
        }
        if (idx < e) {
            int s0 = __ldg(&g_csr_src[idx]);
            float4 h0 = h16_load4(zp + (size_t)s0 * HID + 4 * lane);
            float4 e0 = h16_load4(ep + (size_t)idx * HID + 4 * lane);
            BNRELU(h0);
            acc.x += fmaxf(h0.x + e0.x, 0.f);
            acc.y += fmaxf(h0.y + e0.y, 0.f);
            acc.z += fmaxf(h0.z + e0.z, 0.f);
            acc.w += fmaxf(h0.w + e0.w, 0.f);
        }
        h16_store4(g_zin16 + (size_t)n * HID + 4 * lane, acc);
    }
    #undef BNRELU
}

// ---------------- MLP via tensor cores (mma.sync m16n8k16) ------------------
#define LDT 136
#define MLP_SMEM_BYTES (4 * HID * LDT * 2 + 2 * HID * 4)
__global__ __launch_bounds__(512, 1)
void mlp_mma_kernel(const __half* __restrict__ W16,
                    const float* __restrict__ B1, const float* __restrict__ B2,
                    float* __restrict__ stats) {
    extern __shared__ __half smh[];
    __half* sW1 = smh;
    __half* sW2 = sW1 + HID * LDT;
    __half* sIn = sW2 + HID * LDT;
    __half* sT  = sIn + HID * LDT;
    float* sB1 = (float*)(sT + HID * LDT);
    float* sB2 = sB1 + HID;

    int tid = threadIdx.x;
    int lane = tid & 31;
    int wid = tid >> 5;
    int wr = wid >> 2;
    int wc = wid & 3;

    for (int i = tid; i < HID * HID; i += 512) {
        int r = i >> 7, c = i & 127;
        sW1[r * LDT + c] = W16[i];
        sW2[r * LDT + c] = W16[HID * HID + i];
    }
    if (tid < HID) { sB1[tid] = B1[tid]; sB2[tid] = B2[tid]; }
    __syncthreads();

    int rpb = (N_NODES + gridDim.x - 1) / gridDim.x;
    int base = blockIdx.x * rpb;
    int rend = min(base + rpb, N_NODES);

    float ls[8], lss[8];
    #pragma unroll
    for (int j = 0; j < 8; j++) { ls[j] = 0.f; lss[j] = 0.f; }

    const int qlane = lane & 3;
    const int rlane = lane >> 2;

    for (int rbase = base; rbase < rend; rbase += HID) {
        for (int i = tid; i < HID * 16; i += 512) {
            int r = i >> 4, q = i & 15;
            int row = rbase + r;
            uint4 v = make_uint4(0u, 0u, 0u, 0u);
            if (row < rend) v = *reinterpret_cast<const uint4*>(g_zin16 + (size_t)row * HID + q * 8);
            *reinterpret_cast<uint4*>(&sIn[r * LDT + q * 8]) = v;
        }
        __syncthreads();

        float acc[2][4][4];
        #pragma unroll
        for (int mb = 0; mb < 2; mb++)
            #pragma unroll
            for (int nb = 0; nb < 4; nb++)
                #pragma unroll
                for (int j = 0; j < 4; j++) acc[mb][nb][j] = 0.f;

        #pragma unroll
        for (int ks = 0; ks < 8; ks++) {
            int k0 = ks * 16;
            unsigned a[2][4];
            #pragma unroll
            for (int mb = 0; mb < 2; mb++) {
                int row = wr * 32 + mb * 16 + (lane & 15);
                unsigned addr = smem_u32(&sIn[row * LDT + k0 + ((lane >> 4) << 3)]);
                ldsm_x4(addr, a[mb][0], a[mb][1], a[mb][2], a[mb][3]);
            }
            unsigned b[4][2];
            #pragma unroll
            for (int np = 0; np < 2; np++) {
                int krow = k0 + (lane & 15);
                int n0 = wc * 32 + np * 16 + ((lane >> 4) << 3);
                unsigned addr = smem_u32(&sW1[krow * LDT + n0]);
                unsigned r0, r1, r2, r3;
                ldsm_x4_t(addr, r0, r1, r2, r3);
                b[2 * np][0] = r0; b[2 * np][1] = r1;
                b[2 * np + 1][0] = r2; b[2 * np + 1][1] = r3;
            }
            #pragma unroll
            for (int mb = 0; mb < 2; mb++)
                #pragma unroll
                for (int nb = 0; nb < 4; nb++)
                    mma16816(acc[mb][nb][0], acc[mb][nb][1], acc[mb][nb][2], acc[mb][nb][3],
                             a[mb][0], a[mb][1], a[mb][2], a[mb][3], b[nb][0], b[nb][1]);
        }
        __syncthreads();
        #pragma unroll
        for (int mb = 0; mb < 2; mb++) {
            #pragma unroll
            for (int nb = 0; nb < 4; nb++) {
                int col = wc * 32 + nb * 8 + 2 * qlane;
                float bx = sB1[col], by = sB1[col + 1];
                int rlo = wr * 32 + mb * 16 + rlane;
                *reinterpret_cast<__half2*>(&sT[rlo * LDT + col]) =
                    __floats2half2_rn(fmaxf(acc[mb][nb][0] + bx, 0.f),
                                      fmaxf(acc[mb][nb][1] + by, 0.f));
                *reinterpret_cast<__half2*>(&sT[(rlo + 8) * LDT + col]) =
                    __floats2half2_rn(fmaxf(acc[mb][nb][2] + bx, 0.f),
                                      fmaxf(acc[mb][nb][3] + by, 0.f));
            }
        }
        __syncthreads();

        #pragma unroll
        for (int mb = 0; mb < 2; mb++)
            #pragma unroll
            for (int nb = 0; nb < 4; nb++)
                #pragma unroll
                for (int j = 0; j < 4; j++) acc[mb][nb][j] = 0.f;

        #pragma unroll
        for (int ks = 0; ks < 8; ks++) {
            int k0 = ks * 16;
            unsigned a[2][4];
            #pragma unroll
            for (int mb = 0; mb < 2; mb++) {
                int row = wr * 32 + mb * 16 + (lane & 15);
                unsigned addr = smem_u32(&sT[row * LDT + k0 + ((lane >> 4) << 3)]);
                ldsm_x4(addr, a[mb][0], a[mb][1], a[mb][2], a[mb][3]);
            }
            unsigned b[4][2];
            #pragma unroll
            for (int np = 0; np < 2; np++) {
                int krow = k0 + (lane & 15);
                int n0 = wc * 32 + np * 16 + ((lane >> 4) << 3);
                unsigned addr = smem_u32(&sW2[krow * LDT + n0]);
                unsigned r0, r1, r2, r3;
                ldsm_x4_t(addr, r0, r1, r2, r3);
                b[2 * np][0] = r0; b[2 * np][1] = r1;
                b[2 * np + 1][0] = r2; b[2 * np + 1][1] = r3;
            }
            #pragma unroll
            for (int mb = 0; mb < 2; mb++)
                #pragma unroll
                for (int nb = 0; nb < 4; nb++)
                    mma16816(acc[mb][nb][0], acc[mb][nb][1], acc[mb][nb][2], acc[mb][nb][3],
                             a[mb][0], a[mb][1], a[mb][2], a[mb][3], b[nb][0], b[nb][1]);
        }
        #pragma unroll
        for (int mb = 0; mb < 2; mb++) {
            #pragma unroll
            for (int nb = 0; nb < 4; nb++) {
                int col = wc * 32 + nb * 8 + 2 * qlane;
                float bx = sB2[col], by = sB2[col + 1];
                int rlo = rbase + wr * 32 + mb * 16 + rlane;
                float z0 = acc[mb][nb][0] + bx, z1 = acc[mb][nb][1] + by;
                float z2 = acc[mb][nb][2] + bx, z3 = acc[mb][nb][3] + by;
                if (rlo < rend) {
                    *reinterpret_cast<__half2*>(&g_z16[(size_t)rlo * HID + col]) =
                        __floats2half2_rn(z0, z1);
                    ls[2 * nb] += z0; lss[2 * nb] += z0 * z0;
                    ls[2 * nb + 1] += z1; lss[2 * nb + 1] += z1 * z1;
                }
                if (rlo + 8 < rend) {
                    *reinterpret_cast<__half2*>(&g_z16[(size_t)(rlo + 8) * HID + col]) =
                        __floats2half2_rn(z2, z3);
                    ls[2 * nb] += z2; lss[2 * nb] += z2 * z2;
                    ls[2 * nb + 1] += z3; lss[2 * nb + 1] += z3 * z3;
                }
            }
        }
        __syncthreads();
    }

    #pragma unroll
    for (int j = 0; j < 8; j++) {
        #pragma unroll
        for (int o = 4; o < 32; o <<= 1) {
            ls[j]  += __shfl_xor_sync(0xffffffffu, ls[j], o);
            lss[j] += __shfl_xor_sync(0xffffffffu, lss[j], o);
        }
    }
    if (lane < 4) {
        #pragma unroll
        for (int nb = 0; nb < 4; nb++) {
            #pragma unroll
            for (int j = 0; j < 2; j++) {
                int col = wc * 32 + nb * 8 + 2 * lane + j;
                atomicAdd(&stats[col], ls[2 * nb + j]);
                atomicAdd(&stats[HID + col], lss[2 * nb + j]);
            }
        }
    }
}

// ---------------- last layer: BN + relu + pool (reads z16) ------------------
__global__ void bn_pool_kernel(const float* __restrict__ gamma,
                               const float* __restrict__ beta,
                               const float* __restrict__ stats,
                               const int* __restrict__ batch) {
    int i = blockIdx.x * blockDim.x + threadIdx.x;
    const int n4 = N_NODES * HID / 4;
    if (i >= n4) return;
    int n = i >> 5;
    int c0 = (i & 31) * 4;
    float4 z = h16_load4(g_z16 + (size_t)i * 4);
    float za[4] = {z.x, z.y, z.z, z.w};
    float out[4];
    const float invN = 1.0f / (float)N_NODES;
    #pragma unroll
    for (int j = 0; j < 4; j++) {
        int c = c0 + j;
        float mean = stats[c] * invN;
        float var = stats[HID + c] * invN - mean * mean;
        float rstd = rsqrtf(var + BN_EPS);
        float o = gamma[c] * (za[j] - mean) * rstd + beta[c];
        out[j] = fmaxf(o, 0.f);
    }
    int gi = __ldg(&batch[n]);
    red_add_v4(g_pool + (size_t)gi * HID + c0,
               make_float4(out[0], out[1], out[2], out[3]));
}

// ---------------- head: out = relu(g@W1+b1)@W2+b2 ---------------------------
__global__ void head_kernel(const float* __restrict__ w1, const float* __restrict__ b1,
                            const float* __restrict__ w2, const float* __restrict__ b2,
                            float* __restrict__ out) {
    __shared__ float srow[HID];
    __shared__ float st[HID];
    int gi = blockIdx.x;
    int c = threadIdx.x;
    srow[c] = g_pool[(size_t)gi * HID + c];
    __syncthreads();
    float acc = b1[c];
    for (int k = 0; k < HID; k++) acc += srow[k] * w1[k * HID + c];
    st[c] = fmaxf(acc, 0.f);
    __syncthreads();
    if (c < 2) {
        float o = b2[c];
        for (int k = 0; k < HID; k++) o += st[k] * w2[k * 2 + c];
        out[gi * 2 + c] = o;
    }
}

// ---------------- launch -----------------------------------------------------
extern "C" void kernel_launch(void* const* d_in, const int* in_sizes, int n_in,
                              void* d_out, int out_size) {
    const float* x        = (const float*)d_in[0];
    const int*   eidx     = (const int*)d_in[1];
    const float* eattr    = (const float*)d_in[2];
    const int*   batch    = (const int*)d_in[3];
    const float* node_w   = (const float*)d_in[4];
    const float* node_b   = (const float*)d_in[5];
    const float* edge_w   = (const float*)d_in[6];
    const float* edge_b   = (const float*)d_in[7];
    const float* mlp_w1   = (const float*)d_in[8];
    const float* mlp_b1   = (const float*)d_in[9];
    const float* mlp_w2   = (const float*)d_in[10];
    const float* mlp_b2   = (const float*)d_in[11];
    const float* bn_gamma = (const float*)d_in[12];
    const float* bn_beta  = (const float*)d_in[13];
    const float* head_w1  = (const float*)d_in[14];
    const float* head_b1  = (const float*)d_in[15];
    const float* head_w2  = (const float*)d_in[16];
    const float* head_b2  = (const float*)d_in[17];
    float* out = (float*)d_out;

    cudaFuncSetAttribute(mlp_mma_kernel, cudaFuncAttributeMaxDynamicSharedMemorySize,
                         MLP_SMEM_BYTES);

    float* d_stats;
    cudaGetSymbolAddress((void**)&d_stats, g_stats);
    __half* d_w16;
    cudaGetSymbolAddress((void**)&d_w16, g_w16);

    // launch 0: convert weights + zero cnt/pool/stats
    convert_w_kernel<<<(2 * NLAYERS * HID * HID + 255) / 256, 256>>>(mlp_w1, mlp_w2);
    // launches 1-4: CSR build
    csr_count_kernel<<<(N_EDGES + 255) / 256, 256>>>(eidx);
    chunk_sum_kernel<<<NCHUNK / 128, 128>>>();
    chunk_scan_kernel<<<1, NCHUNK>>>();
    chunk_offs_kernel<<<NCHUNK / 128, 128>>>();
    // launch 5: fused fill + edge encoder (profiler target)
    edge_enc_fill_kernel<<<2048, 256>>>(eattr, eidx, edge_w, edge_b);
    // launch 6: node encoder
    encoder_kernel<<<512, 256>>>(x, node_w, node_b);

    for (int l = 0; l < NLAYERS; l++) {
        if (l == 0) {
            agg_kernel<false><<<2048, 256>>>(nullptr, nullptr, nullptr);
        } else {
            agg_kernel<true><<<2048, 256>>>(bn_gamma + (size_t)(l - 1) * HID,
                                            bn_beta + (size_t)(l - 1) * HID,
                                            d_stats + (size_t)(l - 1) * 2 * HID);
        }
        mlp_mma_kernel<<<148, 512, MLP_SMEM_BYTES>>>(
            d_w16 + (size_t)l * 2 * HID * HID,
            mlp_b1 + (size_t)l * HID,
            mlp_b2 + (size_t)l * HID,
            d_stats + (size_t)l * 2 * HID);
    }

    bn_pool_kernel<<<(N_NODES * HID / 4 + 255) / 256, 256>>>(
        bn_gamma + (size_t)(NLAYERS - 1) * HID,
        bn_beta + (size_t)(NLAYERS - 1) * HID,
        d_stats + (size_t)(NLAYERS - 1) * 2 * HID, batch);
    head_kernel<<<NGRAPHS, HID>>>(head_w1, head_b1, head_w2, head_b2, out);
}

// round 13
// speedup vs baseline: 1.1611x; 1.0413x over previous
#include <cuda_runtime.h>
#include <cuda_fp16.h>

#define N_NODES 50000
#define N_EDGES 600000
#define HID 128
#define NODE_DIM 64
#define EDGE_DIM 16
#define NLAYERS 3
#define NGRAPHS 256
#define BN_EPS 1e-5f

typedef unsigned long long u64;

// ---------------- scratch (device globals; no allocations allowed) ----------
__device__ __half g_z16[N_NODES * HID];    // node features (post bn_apply) / pre-BN z
__device__ __half g_zin16[N_NODES * HID];  // h + agg (MLP input), fp16
__device__ __half g_ea_h[N_EDGES * HID];   // encoded edge features, fp16, CSR order
__device__ __half g_w16[NLAYERS * 2 * HID * HID];  // fp16 MLP weights
__device__ float g_stats[NLAYERS * 2 * HID]; // per-layer column sums / sumsq
__device__ float g_pool[NGRAPHS * HID];    // pooled graph features
// CSR by destination
__device__ int g_cnt[N_NODES];
__device__ int g_off[N_NODES + 1];
__device__ int g_cur[N_NODES];
__device__ int g_csr_src[N_EDGES];
// parallel scan scratch
#define NCHUNK 1024
#define CHSZ ((N_NODES + NCHUNK - 1) / NCHUNK)
__device__ int g_chunk[NCHUNK];
__device__ int g_chunk_base[NCHUNK];

// ---------------- helpers ----------------------------------------------------
__device__ __forceinline__ void red_add_v4(float* p, float4 v) {
    asm volatile("red.global.add.v4.f32 [%0], {%1,%2,%3,%4};"
                 :: "l"(p), "f"(v.x), "f"(v.y), "f"(v.z), "f"(v.w) : "memory");
}

__device__ __forceinline__ float4 h16_load4(const __half* p) {
    uint2 u = *reinterpret_cast<const uint2*>(p);
    __half2 a = *reinterpret_cast<__half2*>(&u.x);
    __half2 b = *reinterpret_cast<__half2*>(&u.y);
    float2 fa = __half22float2(a);
    float2 fb = __half22float2(b);
    return make_float4(fa.x, fa.y, fb.x, fb.y);
}
__device__ __forceinline__ float4 u2_to_f4(uint2 u) {
    __half2 a = *reinterpret_cast<__half2*>(&u.x);
    __half2 b = *reinterpret_cast<__half2*>(&u.y);
    float2 fa = __half22float2(a);
    float2 fb = __half22float2(b);
    return make_float4(fa.x, fa.y, fb.x, fb.y);
}
__device__ __forceinline__ void h16_store4(__half* p, float4 v) {
    union { __half2 h[2]; uint2 u; } cv;
    cv.h[0] = __floats2half2_rn(v.x, v.y);
    cv.h[1] = __floats2half2_rn(v.z, v.w);
    *reinterpret_cast<uint2*>(p) = cv.u;
}

__device__ __forceinline__ unsigned smem_u32(const void* p) {
    return (unsigned)__cvta_generic_to_shared(p);
}
__device__ __forceinline__ void ldsm_x4(unsigned addr, unsigned& r0, unsigned& r1,
                                        unsigned& r2, unsigned& r3) {
    asm volatile("ldmatrix.sync.aligned.m8n8.x4.shared.b16 {%0,%1,%2,%3},[%4];"
                 : "=r"(r0), "=r"(r1), "=r"(r2), "=r"(r3) : "r"(addr));
}
__device__ __forceinline__ void ldsm_x4_t(unsigned addr, unsigned& r0, unsigned& r1,
                                          unsigned& r2, unsigned& r3) {
    asm volatile("ldmatrix.sync.aligned.m8n8.x4.trans.shared.b16 {%0,%1,%2,%3},[%4];"
                 : "=r"(r0), "=r"(r1), "=r"(r2), "=r"(r3) : "r"(addr));
}
__device__ __forceinline__ void mma16816(float& c0, float& c1, float& c2, float& c3,
                                         unsigned a0, unsigned a1, unsigned a2, unsigned a3,
                                         unsigned b0, unsigned b1) {
    asm volatile("mma.sync.aligned.m16n8k16.row.col.f32.f16.f16.f32 "
                 "{%0,%1,%2,%3},{%4,%5,%6,%7},{%8,%9},{%0,%1,%2,%3};"
                 : "+f"(c0), "+f"(c1), "+f"(c2), "+f"(c3)
                 : "r"(a0), "r"(a1), "r"(a2), "r"(a3), "r"(b0), "r"(b1));
}

// ---------------- weight conversion + zeroing (launch 0) --------------------
__global__ void convert_w_kernel(const float* __restrict__ w1,
                                 const float* __restrict__ w2) {
    int gt = blockIdx.x * blockDim.x + threadIdx.x;
    int gsz = gridDim.x * blockDim.x;
    for (int i = gt; i < N_NODES; i += gsz) g_cnt[i] = 0;
    for (int i = gt; i < NGRAPHS * HID; i += gsz) g_pool[i] = 0.f;
    for (int i = gt; i < NLAYERS * 2 * HID; i += gsz) g_stats[i] = 0.f;

    int i = gt;
    const int per = NLAYERS * HID * HID;
    if (i < per) {
        int l = i / (HID * HID);
        int j = i % (HID * HID);
        g_w16[(size_t)l * 2 * HID * HID + j] = __float2half(w1[i]);
    } else if (i < 2 * per) {
        int k = i - per;
        int l = k / (HID * HID);
        int j = k % (HID * HID);
        g_w16[(size_t)l * 2 * HID * HID + HID * HID + j] = __float2half(w2[k]);
    }
}

// ---------------- CSR build --------------------------------------------------
__global__ void csr_count_kernel(const int* __restrict__ eidx) {
    int e = blockIdx.x * blockDim.x + threadIdx.x;
    if (e < N_EDGES) atomicAdd(&g_cnt[eidx[N_EDGES + e]], 1);
}

__global__ void chunk_sum_kernel() {
    int t = blockIdx.x * blockDim.x + threadIdx.x;
    if (t >= NCHUNK) return;
    int beg = t * CHSZ;
    int end = min(beg + CHSZ, N_NODES);
    int s = 0;
    for (int i = beg; i < end; i++) s += g_cnt[i];
    g_chunk[t] = s;
}

__global__ void chunk_scan_kernel() {
    __shared__ int ssum[NCHUNK];
    int t = threadIdx.x;
    ssum[t] = g_chunk[t];
    __syncthreads();
    for (int off = 1; off < NCHUNK; off <<= 1) {
        int v = (t >= off) ? ssum[t - off] : 0;
        __syncthreads();
        ssum[t] += v;
        __syncthreads();
    }
    g_chunk_base[t] = (t == 0) ? 0 : ssum[t - 1];
    if (t == NCHUNK - 1) g_off[N_NODES] = ssum[t];
}

__global__ void chunk_offs_kernel() {
    int t = blockIdx.x * blockDim.x + threadIdx.x;
    if (t >= NCHUNK) return;
    int beg = t * CHSZ;
    int end = min(beg + CHSZ, N_NODES);
    int run = g_chunk_base[t];
    for (int i = beg; i < end; i++) {
        g_off[i] = run;
        g_cur[i] = run;
        run += g_cnt[i];
    }
}

// --- fused: csr_fill + edge encoder -> fp16 rows in CSR order ---------------
__global__ void edge_enc_fill_kernel(const float* __restrict__ eattr,
                                     const int* __restrict__ eidx,
                                     const float* __restrict__ W,
                                     const float* __restrict__ b) {
    __shared__ float sW[EDGE_DIM * HID];
    __shared__ float sb[HID];
    for (int i = threadIdx.x; i < EDGE_DIM * HID; i += blockDim.x) sW[i] = W[i];
    if (threadIdx.x < HID) sb[threadIdx.x] = b[threadIdx.x];
    __syncthreads();
    int lane = threadIdx.x & 31;
    int warp = (blockIdx.x * blockDim.x + threadIdx.x) >> 5;
    int nw = (gridDim.x * blockDim.x) >> 5;
    float4 bb = reinterpret_cast<const float4*>(sb)[lane];
    for (int e = warp; e < N_EDGES; e += nw) {
        int slot = 0;
        if (lane == 0) {
            int src = eidx[e];
            int dst = eidx[N_EDGES + e];
            slot = atomicAdd(&g_cur[dst], 1);
            g_csr_src[slot] = src;
        }
        slot = __shfl_sync(0xffffffffu, slot, 0);
        const float4* ar = reinterpret_cast<const float4*>(eattr + (size_t)e * EDGE_DIM);
        float4 acc = bb;
        #pragma unroll
        for (int kk = 0; kk < EDGE_DIM / 4; kk++) {
            float4 av = ar[kk];
            float xa[4] = {av.x, av.y, av.z, av.w};
            #pragma unroll
            for (int j = 0; j < 4; j++) {
                float4 w = *reinterpret_cast<const float4*>(&sW[(4 * kk + j) * HID + 4 * lane]);
                acc.x += xa[j] * w.x;
                acc.y += xa[j] * w.y;
                acc.z += xa[j] * w.z;
                acc.w += xa[j] * w.w;
            }
        }
        h16_store4(g_ea_h + (size_t)slot * HID + 4 * lane, acc);
    }
}

// ---------------- node encoder: z16 = x @ node_w + node_b -------------------
__global__ void encoder_kernel(const float* __restrict__ x,
                               const float* __restrict__ W,
                               const float* __restrict__ b) {
    __shared__ float sW[NODE_DIM * HID];
    for (int i = threadIdx.x; i < NODE_DIM * HID; i += blockDim.x) sW[i] = W[i];
    __syncthreads();
    int lane = threadIdx.x & 31;
    int warp = (blockIdx.x * blockDim.x + threadIdx.x) >> 5;
    int nw = (gridDim.x * blockDim.x) >> 5;
    float4 bb = reinterpret_cast<const float4*>(b)[lane];
    for (int n = warp; n < N_NODES; n += nw) {
        const float4* xr = reinterpret_cast<const float4*>(x + (size_t)n * NODE_DIM);
        float4 acc = bb;
        #pragma unroll
        for (int kk = 0; kk < NODE_DIM / 4; kk++) {
            float4 xv = xr[kk];
            float xa[4] = {xv.x, xv.y, xv.z, xv.w};
            #pragma unroll
            for (int j = 0; j < 4; j++) {
                float4 w = *reinterpret_cast<const float4*>(&sW[(4 * kk + j) * HID + 4 * lane]);
                acc.x += xa[j] * w.x;
                acc.y += xa[j] * w.y;
                acc.z += xa[j] * w.z;
                acc.w += xa[j] * w.w;
            }
        }
        h16_store4(g_z16 + (size_t)n * HID + 4 * lane, acc);
    }
}

// ---- bn_apply: z16 <- relu(bn(z16)) in place (layers 0..NLAYERS-2) ---------
__global__ void bn_apply_kernel(const float* __restrict__ gamma,
                                const float* __restrict__ beta,
                                const float* __restrict__ stats) {
    int i = blockIdx.x * blockDim.x + threadIdx.x;
    const int n4 = N_NODES * HID / 4;
    if (i >= n4) return;
    int c0 = (i & 31) * 4;
    float4 z = h16_load4(g_z16 + (size_t)i * 4);
    float za[4] = {z.x, z.y, z.z, z.w};
    float out[4];
    const float invN = 1.0f / (float)N_NODES;
    #pragma unroll
    for (int j = 0; j < 4; j++) {
        int c = c0 + j;
        float mean = stats[c] * invN;
        float var = stats[HID + c] * invN - mean * mean;
        float rstd = rsqrtf(var + BN_EPS);
        float o = gamma[c] * (za[j] - mean) * rstd + beta[c];
        out[j] = fmaxf(o, 0.f);
    }
    h16_store4(g_z16 + (size_t)i * 4, make_float4(out[0], out[1], out[2], out[3]));
}

// ---- aggregation (BN-free): zin[n] = h[n] + sum_{e->n} relu(h[src]+ea[e]) --
// register-lean: gathers held as uint2, converted at consumption.
__global__ __launch_bounds__(256, 4)
void agg_kernel() {
    int lane = threadIdx.x & 31;
    int warp = (blockIdx.x * blockDim.x + threadIdx.x) >> 5;
    int nw = (gridDim.x * blockDim.x) >> 5;
    const __half* zp = g_z16;
    const __half* ep = g_ea_h;
    const int col = 4 * lane;

    for (int n = warp; n < N_NODES; n += nw) {
        float4 acc = u2_to_f4(*reinterpret_cast<const uint2*>(zp + (size_t)n * HID + col));
        int s = __ldg(&g_off[n]);
        int e = __ldg(&g_off[n + 1]);
        int idx = s;
        for (; idx + 4 <= e; idx += 4) {
            int s0 = __ldg(&g_csr_src[idx]);
            int s1 = __ldg(&g_csr_src[idx + 1]);
            int s2 = __ldg(&g_csr_src[idx + 2]);
            int s3 = __ldg(&g_csr_src[idx + 3]);
            uint2 H0 = *reinterpret_cast<const uint2*>(zp + (size_t)s0 * HID + col);
            uint2 H1 = *reinterpret_cast<const uint2*>(zp + (size_t)s1 * HID + col);
            uint2 H2 = *reinterpret_cast<const uint2*>(zp + (size_t)s2 * HID + col);
            uint2 H3 = *reinterpret_cast<const uint2*>(zp + (size_t)s3 * HID + col);
            uint2 E0 = *reinterpret_cast<const uint2*>(ep + (size_t)(idx + 0) * HID + col);
            uint2 E1 = *reinterpret_cast<const uint2*>(ep + (size_t)(idx + 1) * HID + col);
            uint2 E2 = *reinterpret_cast<const uint2*>(ep + (size_t)(idx + 2) * HID + col);
            uint2 E3 = *reinterpret_cast<const uint2*>(ep + (size_t)(idx + 3) * HID + col);
            {
                float4 h = u2_to_f4(H0), ev = u2_to_f4(E0);
                acc.x += fmaxf(h.x + ev.x, 0.f);
                acc.y += fmaxf(h.y + ev.y, 0.f);
                acc.z += fmaxf(h.z + ev.z, 0.f);
                acc.w += fmaxf(h.w + ev.w, 0.f);
            }
            {
                float4 h = u2_to_f4(H1), ev = u2_to_f4(E1);
                acc.x += fmaxf(h.x + ev.x, 0.f);
                acc.y += fmaxf(h.y + ev.y, 0.f);
                acc.z += fmaxf(h.z + ev.z, 0.f);
                acc.w += fmaxf(h.w + ev.w, 0.f);
            }
            {
                float4 h = u2_to_f4(H2), ev = u2_to_f4(E2);
                acc.x += fmaxf(h.x + ev.x, 0.f);
                acc.y += fmaxf(h.y + ev.y, 0.f);
                acc.z += fmaxf(h.z + ev.z, 0.f);
                acc.w += fmaxf(h.w + ev.w, 0.f);
            }
            {
                float4 h = u2_to_f4(H3), ev = u2_to_f4(E3);
                acc.x += fmaxf(h.x + ev.x, 0.f);
                acc.y += fmaxf(h.y + ev.y, 0.f);
                acc.z += fmaxf(h.z + ev.z, 0.f);
                acc.w += fmaxf(h.w + ev.w, 0.f);
            }
        }
        if (idx + 2 <= e) {
            int s0 = __ldg(&g_csr_src[idx]);
            int s1 = __ldg(&g_csr_src[idx + 1]);
            uint2 H0 = *reinterpret_cast<const uint2*>(zp + (size_t)s0 * HID + col);
            uint2 H1 = *reinterpret_cast<const uint2*>(zp + (size_t)s1 * HID + col);
            uint2 E0 = *reinterpret_cast<const uint2*>(ep + (size_t)(idx + 0) * HID + col);
            uint2 E1 = *reinterpret_cast<const uint2*>(ep + (size_t)(idx + 1) * HID + col);
            {
                float4 h = u2_to_f4(H0), ev = u2_to_f4(E0);
                acc.x += fmaxf(h.x + ev.x, 0.f);
                acc.y += fmaxf(h.y + ev.y, 0.f);
                acc.z += fmaxf(h.z + ev.z, 0.f);
                acc.w += fmaxf(h.w + ev.w, 0.f);
            }
            {
                float4 h = u2_to_f4(H1), ev = u2_to_f4(E1);
                acc.x += fmaxf(h.x + ev.x, 0.f);
                acc.y += fmaxf(h.y + ev.y, 0.f);
                acc.z += fmaxf(h.z + ev.z, 0.f);
                acc.w += fmaxf(h.w + ev.w, 0.f);
            }
            idx += 2;
        }
        if (idx < e) {
            int s0 = __ldg(&g_csr_src[idx]);
            float4 h = u2_to_f4(*reinterpret_cast<const uint2*>(zp + (size_t)s0 * HID + col));
            float4 ev = u2_to_f4(*reinterpret_cast<const uint2*>(ep + (size_t)idx * HID + col));
            acc.x += fmaxf(h.x + ev.x, 0.f);
            acc.y += fmaxf(h.y + ev.y, 0.f);
            acc.z += fmaxf(h.z + ev.z, 0.f);
            acc.w += fmaxf(h.w + ev.w, 0.f);
        }
        h16_store4(g_zin16 + (size_t)n * HID + col, acc);
    }
}

// ---------------- MLP via tensor cores (mma.sync m16n8k16) ------------------
#define LDT 136
#define MLP_SMEM_BYTES (4 * HID * LDT * 2 + 2 * HID * 4)
__global__ __launch_bounds__(512, 1)
void mlp_mma_kernel(const __half* __restrict__ W16,
                    const float* __restrict__ B1, const float* __restrict__ B2,
                    float* __restrict__ stats) {
    extern __shared__ __half smh[];
    __half* sW1 = smh;
    __half* sW2 = sW1 + HID * LDT;
    __half* sIn = sW2 + HID * LDT;
    __half* sT  = sIn + HID * LDT;
    float* sB1 = (float*)(sT + HID * LDT);
    float* sB2 = sB1 + HID;

    int tid = threadIdx.x;
    int lane = tid & 31;
    int wid = tid >> 5;
    int wr = wid >> 2;
    int wc = wid & 3;

    for (int i = tid; i < HID * HID; i += 512) {
        int r = i >> 7, c = i & 127;
        sW1[r * LDT + c] = W16[i];
        sW2[r * LDT + c] = W16[HID * HID + i];
    }
    if (tid < HID) { sB1[tid] = B1[tid]; sB2[tid] = B2[tid]; }
    __syncthreads();

    int rpb = (N_NODES + gridDim.x - 1) / gridDim.x;
    int base = blockIdx.x * rpb;
    int rend = min(base + rpb, N_NODES);

    float ls[8], lss[8];
    #pragma unroll
    for (int j = 0; j < 8; j++) { ls[j] = 0.f; lss[j] = 0.f; }

    const int qlane = lane & 3;
    const int rlane = lane >> 2;

    for (int rbase = base; rbase < rend; rbase += HID) {
        for (int i = tid; i < HID * 16; i += 512) {
            int r = i >> 4, q = i & 15;
            int row = rbase + r;
            uint4 v = make_uint4(0u, 0u, 0u, 0u);
            if (row < rend) v = *reinterpret_cast<const uint4*>(g_zin16 + (size_t)row * HID + q * 8);
            *reinterpret_cast<uint4*>(&sIn[r * LDT + q * 8]) = v;
        }
        __syncthreads();

        float acc[2][4][4];
        #pragma unroll
        for (int mb = 0; mb < 2; mb++)
            #pragma unroll
            for (int nb = 0; nb < 4; nb++)
                #pragma unroll
                for (int j = 0; j < 4; j++) acc[mb][nb][j] = 0.f;

        #pragma unroll
        for (int ks = 0; ks < 8; ks++) {
            int k0 = ks * 16;
            unsigned a[2][4];
            #pragma unroll
            for (int mb = 0; mb < 2; mb++) {
                int row = wr * 32 + mb * 16 + (lane & 15);
                unsigned addr = smem_u32(&sIn[row * LDT + k0 + ((lane >> 4) << 3)]);
                ldsm_x4(addr, a[mb][0], a[mb][1], a[mb][2], a[mb][3]);
            }
            unsigned b[4][2];
            #pragma unroll
            for (int np = 0; np < 2; np++) {
                int krow = k0 + (lane & 15);
                int n0 = wc * 32 + np * 16 + ((lane >> 4) << 3);
                unsigned addr = smem_u32(&sW1[krow * LDT + n0]);
                unsigned r0, r1, r2, r3;
                ldsm_x4_t(addr, r0, r1, r2, r3);
                b[2 * np][0] = r0; b[2 * np][1] = r1;
                b[2 * np + 1][0] = r2; b[2 * np + 1][1] = r3;
            }
            #pragma unroll
            for (int mb = 0; mb < 2; mb++)
                #pragma unroll
                for (int nb = 0; nb < 4; nb++)
                    mma16816(acc[mb][nb][0], acc[mb][nb][1], acc[mb][nb][2], acc[mb][nb][3],
                             a[mb][0], a[mb][1], a[mb][2], a[mb][3], b[nb][0], b[nb][1]);
        }
        __syncthreads();
        #pragma unroll
        for (int mb = 0; mb < 2; mb++) {
            #pragma unroll
            for (int nb = 0; nb < 4; nb++) {
                int col = wc * 32 + nb * 8 + 2 * qlane;
                float bx = sB1[col], by = sB1[col + 1];
                int rlo = wr * 32 + mb * 16 + rlane;
                *reinterpret_cast<__half2*>(&sT[rlo * LDT + col]) =
                    __floats2half2_rn(fmaxf(acc[mb][nb][0] + bx, 0.f),
                                      fmaxf(acc[mb][nb][1] + by, 0.f));
                *reinterpret_cast<__half2*>(&sT[(rlo + 8) * LDT + col]) =
                    __floats2half2_rn(fmaxf(acc[mb][nb][2] + bx, 0.f),
                                      fmaxf(acc[mb][nb][3] + by, 0.f));
            }
        }
        __syncthreads();

        #pragma unroll
        for (int mb = 0; mb < 2; mb++)
            #pragma unroll
            for (int nb = 0; nb < 4; nb++)
                #pragma unroll
                for (int j = 0; j < 4; j++) acc[mb][nb][j] = 0.f;

        #pragma unroll
        for (int ks = 0; ks < 8; ks++) {
            int k0 = ks * 16;
            unsigned a[2][4];
            #pragma unroll
            for (int mb = 0; mb < 2; mb++) {
                int row = wr * 32 + mb * 16 + (lane & 15);
                unsigned addr = smem_u32(&sT[row * LDT + k0 + ((lane >> 4) << 3)]);
                ldsm_x4(addr, a[mb][0], a[mb][1], a[mb][2], a[mb][3]);
            }
            unsigned b[4][2];
            #pragma unroll
            for (int np = 0; np < 2; np++) {
                int krow = k0 + (lane & 15);
                int n0 = wc * 32 + np * 16 + ((lane >> 4) << 3);
                unsigned addr = smem_u32(&sW2[krow * LDT + n0]);
                unsigned r0, r1, r2, r3;
                ldsm_x4_t(addr, r0, r1, r2, r3);
                b[2 * np][0] = r0; b[2 * np][1] = r1;
                b[2 * np + 1][0] = r2; b[2 * np + 1][1] = r3;
            }
            #pragma unroll
            for (int mb = 0; mb < 2; mb++)
                #pragma unroll
                for (int nb = 0; nb < 4; nb++)
                    mma16816(acc[mb][nb][0], acc[mb][nb][1], acc[mb][nb][2], acc[mb][nb][3],
                             a[mb][0], a[mb][1], a[mb][2], a[mb][3], b[nb][0], b[nb][1]);
        }
        #pragma unroll
        for (int mb = 0; mb < 2; mb++) {
            #pragma unroll
            for (int nb = 0; nb < 4; nb++) {
                int col = wc * 32 + nb * 8 + 2 * qlane;
                float bx = sB2[col], by = sB2[col + 1];
                int rlo = rbase + wr * 32 + mb * 16 + rlane;
                float z0 = acc[mb][nb][0] + bx, z1 = acc[mb][nb][1] + by;
                float z2 = acc[mb][nb][2] + bx, z3 = acc[mb][nb][3] + by;
                if (rlo < rend) {
                    *reinterpret_cast<__half2*>(&g_z16[(size_t)rlo * HID + col]) =
                        __floats2half2_rn(z0, z1);
                    ls[2 * nb] += z0; lss[2 * nb] += z0 * z0;
                    ls[2 * nb + 1] += z1; lss[2 * nb + 1] += z1 * z1;
                }
                if (rlo + 8 < rend) {
                    *reinterpret_cast<__half2*>(&g_z16[(size_t)(rlo + 8) * HID + col]) =
                        __floats2half2_rn(z2, z3);
                    ls[2 * nb] += z2; lss[2 * nb] += z2 * z2;
                    ls[2 * nb + 1] += z3; lss[2 * nb + 1] += z3 * z3;
                }
            }
        }
        __syncthreads();
    }

    #pragma unroll
    for (int j = 0; j < 8; j++) {
        #pragma unroll
        for (int o = 4; o < 32; o <<= 1) {
            ls[j]  += __shfl_xor_sync(0xffffffffu, ls[j], o);
            lss[j] += __shfl_xor_sync(0xffffffffu, lss[j], o);
        }
    }
    if (lane < 4) {
        #pragma unroll
        for (int nb = 0; nb < 4; nb++) {
            #pragma unroll
            for (int j = 0; j < 2; j++) {
                int col = wc * 32 + nb * 8 + 2 * lane + j;
                atomicAdd(&stats[col], ls[2 * nb + j]);
                atomicAdd(&stats[HID + col], lss[2 * nb + j]);
            }
        }
    }
}

// ---------------- last layer: BN + relu + pool (reads z16) ------------------
__global__ void bn_pool_kernel(const float* __restrict__ gamma,
                               const float* __restrict__ beta,
                               const float* __restrict__ stats,
                               const int* __restrict__ batch) {
    int i = blockIdx.x * blockDim.x + threadIdx.x;
    const int n4 = N_NODES * HID / 4;
    if (i >= n4) return;
    int n = i >> 5;
    int c0 = (i & 31) * 4;
    float4 z = h16_load4(g_z16 + (size_t)i * 4);
    float za[4] = {z.x, z.y, z.z, z.w};
    float out[4];
    const float invN = 1.0f / (float)N_NODES;
    #pragma unroll
    for (int j = 0; j < 4; j++) {
        int c = c0 + j;
        float mean = stats[c] * invN;
        float var = stats[HID + c] * invN - mean * mean;
        float rstd = rsqrtf(var + BN_EPS);
        float o = gamma[c] * (za[j] - mean) * rstd + beta[c];
        out[j] = fmaxf(o, 0.f);
    }
    int gi = __ldg(&batch[n]);
    red_add_v4(g_pool + (size_t)gi * HID + c0,
               make_float4(out[0], out[1], out[2], out[3]));
}

// ---------------- head: out = relu(g@W1+b1)@W2+b2 ---------------------------
__global__ void head_kernel(const float* __restrict__ w1, const float* __restrict__ b1,
                            const float* __restrict__ w2, const float* __restrict__ b2,
                            float* __restrict__ out) {
    __shared__ float srow[HID];
    __shared__ float st[HID];
    int gi = blockIdx.x;
    int c = threadIdx.x;
    srow[c] = g_pool[(size_t)gi * HID + c];
    __syncthreads();
    float acc = b1[c];
    for (int k = 0; k < HID; k++) acc += srow[k] * w1[k * HID + c];
    st[c] = fmaxf(acc, 0.f);
    __syncthreads();
    if (c < 2) {
        float o = b2[c];
        for (int k = 0; k < HID; k++) o += st[k] * w2[k * 2 + c];
        out[gi * 2 + c] = o;
    }
}

// ---------------- launch -----------------------------------------------------
extern "C" void kernel_launch(void* const* d_in, const int* in_sizes, int n_in,
                              void* d_out, int out_size) {
    const float* x        = (const float*)d_in[0];
    const int*   eidx     = (const int*)d_in[1];
    const float* eattr    = (const float*)d_in[2];
    const int*   batch    = (const int*)d_in[3];
    const float* node_w   = (const float*)d_in[4];
    const float* node_b   = (const float*)d_in[5];
    const float* edge_w   = (const float*)d_in[6];
    const float* edge_b   = (const float*)d_in[7];
    const float* mlp_w1   = (const float*)d_in[8];
    const float* mlp_b1   = (const float*)d_in[9];
    const float* mlp_w2   = (const float*)d_in[10];
    const float* mlp_b2   = (const float*)d_in[11];
    const float* bn_gamma = (const float*)d_in[12];
    const float* bn_beta  = (const float*)d_in[13];
    const float* head_w1  = (const float*)d_in[14];
    const float* head_b1  = (const float*)d_in[15];
    const float* head_w2  = (const float*)d_in[16];
    const float* head_b2  = (const float*)d_in[17];
    float* out = (float*)d_out;

    cudaFuncSetAttribute(mlp_mma_kernel, cudaFuncAttributeMaxDynamicSharedMemorySize,
                         MLP_SMEM_BYTES);

    float* d_stats;
    cudaGetSymbolAddress((void**)&d_stats, g_stats);
    __half* d_w16;
    cudaGetSymbolAddress((void**)&d_w16, g_w16);

    convert_w_kernel<<<(2 * NLAYERS * HID * HID + 255) / 256, 256>>>(mlp_w1, mlp_w2);
    csr_count_kernel<<<(N_EDGES + 255) / 256, 256>>>(eidx);
    chunk_sum_kernel<<<NCHUNK / 128, 128>>>();
    chunk_scan_kernel<<<1, NCHUNK>>>();
    chunk_offs_kernel<<<NCHUNK / 128, 128>>>();
    edge_enc_fill_kernel<<<2048, 256>>>(eattr, eidx, edge_w, edge_b);
    encoder_kernel<<<512, 256>>>(x, node_w, node_b);

    const int grid_elem = (N_NODES * HID / 4 + 255) / 256;
    for (int l = 0; l < NLAYERS; l++) {
        agg_kernel<<<4096, 256>>>();
        mlp_mma_kernel<<<148, 512, MLP_SMEM_BYTES>>>(
            d_w16 + (size_t)l * 2 * HID * HID,
            mlp_b1 + (size_t)l * HID,
            mlp_b2 + (size_t)l * HID,
            d_stats + (size_t)l * 2 * HID);
        if (l < NLAYERS - 1) {
            bn_apply_kernel<<<grid_elem, 256>>>(bn_gamma + (size_t)l * HID,
                                                bn_beta + (size_t)l * HID,
                                                d_stats + (size_t)l * 2 * HID);
        }
    }

    bn_pool_kernel<<<grid_elem, 256>>>(
        bn_gamma + (size_t)(NLAYERS - 1) * HID,
        bn_beta + (size_t)(NLAYERS - 1) * HID,
        d_stats + (size_t)(NLAYERS - 1) * 2 * HID, batch);
    head_kernel<<<NGRAPHS, HID>>>(head_w1, head_b1, head_w2, head_b2, out);
}

// round 14
// speedup vs baseline: 1.3227x; 1.1392x over previous
#include <cuda_runtime.h>
#include <cuda_fp16.h>

#define N_NODES 50000
#define N_EDGES 600000
#define HID 128
#define NODE_DIM 64
#define EDGE_DIM 16
#define NLAYERS 3
#define NGRAPHS 256
#define BN_EPS 1e-5f

typedef unsigned long long u64;

// ---------------- scratch (device globals; no allocations allowed) ----------
__device__ __half g_z16[N_NODES * HID];    // node features (post bn_apply) / pre-BN z
__device__ __half g_zin16[N_NODES * HID];  // h + agg (MLP input), fp16
__device__ __half g_ea_h[N_EDGES * HID];   // encoded edge features, fp16, CSR order
__device__ __half g_w16[NLAYERS * 2 * HID * HID];  // fp16 MLP weights
__device__ float g_stats[NLAYERS * 2 * HID]; // per-layer column sums / sumsq
__device__ float g_pool[NGRAPHS * HID];    // pooled graph features
// CSR by destination
__device__ int g_cnt[N_NODES];
__device__ int g_off[N_NODES + 1];
__device__ int g_cur[N_NODES];
__device__ int g_csr_src[N_EDGES];
// parallel scan scratch
#define NCHUNK 1024
#define CHSZ ((N_NODES + NCHUNK - 1) / NCHUNK)
__device__ int g_chunk[NCHUNK];
__device__ int g_chunk_base[NCHUNK];

// ---------------- helpers ----------------------------------------------------
__device__ __forceinline__ void red_add_v4(float* p, float4 v) {
    asm volatile("red.global.add.v4.f32 [%0], {%1,%2,%3,%4};"
                 :: "l"(p), "f"(v.x), "f"(v.y), "f"(v.z), "f"(v.w) : "memory");
}

__device__ __forceinline__ float4 h16_load4(const __half* p) {
    uint2 u = *reinterpret_cast<const uint2*>(p);
    __half2 a = *reinterpret_cast<__half2*>(&u.x);
    __half2 b = *reinterpret_cast<__half2*>(&u.y);
    float2 fa = __half22float2(a);
    float2 fb = __half22float2(b);
    return make_float4(fa.x, fa.y, fb.x, fb.y);
}
__device__ __forceinline__ float4 u2_to_f4(uint2 u) {
    __half2 a = *reinterpret_cast<__half2*>(&u.x);
    __half2 b = *reinterpret_cast<__half2*>(&u.y);
    float2 fa = __half22float2(a);
    float2 fb = __half22float2(b);
    return make_float4(fa.x, fa.y, fb.x, fb.y);
}
__device__ __forceinline__ void h16_store4(__half* p, float4 v) {
    union { __half2 h[2]; uint2 u; } cv;
    cv.h[0] = __floats2half2_rn(v.x, v.y);
    cv.h[1] = __floats2half2_rn(v.z, v.w);
    *reinterpret_cast<uint2*>(p) = cv.u;
}

__device__ __forceinline__ unsigned smem_u32(const void* p) {
    return (unsigned)__cvta_generic_to_shared(p);
}
__device__ __forceinline__ void ldsm_x4(unsigned addr, unsigned& r0, unsigned& r1,
                                        unsigned& r2, unsigned& r3) {
    asm volatile("ldmatrix.sync.aligned.m8n8.x4.shared.b16 {%0,%1,%2,%3},[%4];"
                 : "=r"(r0), "=r"(r1), "=r"(r2), "=r"(r3) : "r"(addr));
}
__device__ __forceinline__ void ldsm_x4_t(unsigned addr, unsigned& r0, unsigned& r1,
                                          unsigned& r2, unsigned& r3) {
    asm volatile("ldmatrix.sync.aligned.m8n8.x4.trans.shared.b16 {%0,%1,%2,%3},[%4];"
                 : "=r"(r0), "=r"(r1), "=r"(r2), "=r"(r3) : "r"(addr));
}
__device__ __forceinline__ void mma16816(float& c0, float& c1, float& c2, float& c3,
                                         unsigned a0, unsigned a1, unsigned a2, unsigned a3,
                                         unsigned b0, unsigned b1) {
    asm volatile("mma.sync.aligned.m16n8k16.row.col.f32.f16.f16.f32 "
                 "{%0,%1,%2,%3},{%4,%5,%6,%7},{%8,%9},{%0,%1,%2,%3};"
                 : "+f"(c0), "+f"(c1), "+f"(c2), "+f"(c3)
                 : "r"(a0), "r"(a1), "r"(a2), "r"(a3), "r"(b0), "r"(b1));
}

// ---------------- weight conversion + zeroing (launch 0) --------------------
__global__ void convert_w_kernel(const float* __restrict__ w1,
                                 const float* __restrict__ w2) {
    int gt = blockIdx.x * blockDim.x + threadIdx.x;
    int gsz = gridDim.x * blockDim.x;
    for (int i = gt; i < N_NODES; i += gsz) g_cnt[i] = 0;
    for (int i = gt; i < NGRAPHS * HID; i += gsz) g_pool[i] = 0.f;
    for (int i = gt; i < NLAYERS * 2 * HID; i += gsz) g_stats[i] = 0.f;

    int i = gt;
    const int per = NLAYERS * HID * HID;
    if (i < per) {
        int l = i / (HID * HID);
        int j = i % (HID * HID);
        g_w16[(size_t)l * 2 * HID * HID + j] = __float2half(w1[i]);
    } else if (i < 2 * per) {
        int k = i - per;
        int l = k / (HID * HID);
        int j = k % (HID * HID);
        g_w16[(size_t)l * 2 * HID * HID + HID * HID + j] = __float2half(w2[k]);
    }
}

// ---------------- CSR build --------------------------------------------------
__global__ void csr_count_kernel(const int* __restrict__ eidx) {
    int e = blockIdx.x * blockDim.x + threadIdx.x;
    if (e < N_EDGES) atomicAdd(&g_cnt[eidx[N_EDGES + e]], 1);
}

__global__ void chunk_sum_kernel() {
    int t = blockIdx.x * blockDim.x + threadIdx.x;
    if (t >= NCHUNK) return;
    int beg = t * CHSZ;
    int end = min(beg + CHSZ, N_NODES);
    int s = 0;
    for (int i = beg; i < end; i++) s += g_cnt[i];
    g_chunk[t] = s;
}

__global__ void chunk_scan_kernel() {
    __shared__ int ssum[NCHUNK];
    int t = threadIdx.x;
    ssum[t] = g_chunk[t];
    __syncthreads();
    for (int off = 1; off < NCHUNK; off <<= 1) {
        int v = (t >= off) ? ssum[t - off] : 0;
        __syncthreads();
        ssum[t] += v;
        __syncthreads();
    }
    g_chunk_base[t] = (t == 0) ? 0 : ssum[t - 1];
    if (t == NCHUNK - 1) g_off[N_NODES] = ssum[t];
}

__global__ void chunk_offs_kernel() {
    int t = blockIdx.x * blockDim.x + threadIdx.x;
    if (t >= NCHUNK) return;
    int beg = t * CHSZ;
    int end = min(beg + CHSZ, N_NODES);
    int run = g_chunk_base[t];
    for (int i = beg; i < end; i++) {
        g_off[i] = run;
        g_cur[i] = run;
        run += g_cnt[i];
    }
}

// --- edge encoder via tensor cores + fused csr_fill --------------------------
// per tile of 128 edges: A[128x16] fp16 @ W[16x128] fp16 -> ea rows scattered
// to CSR slots in fp16.
#define LDTE 136   // sW row stride (halves)
#define LDA 24     // sA row stride (halves): 16 data + 8 pad (conflict-free ldsm)
__global__ __launch_bounds__(512)
void edge_enc_mma_kernel(const float* __restrict__ eattr,
                         const int* __restrict__ eidx,
                         const float* __restrict__ W,
                         const float* __restrict__ b) {
    __shared__ __half sW[EDGE_DIM * LDTE];
    __shared__ __half sA[128 * LDA];
    __shared__ float sbb[HID];
    __shared__ int sslot[128];

    int tid = threadIdx.x;
    int lane = tid & 31;
    int wid = tid >> 5;
    int wr = wid >> 2;   // warp row block 0..3 (32 edges each)
    int wc = wid & 3;    // warp col block 0..3 (32 cols each)

    for (int i = tid; i < EDGE_DIM * HID; i += 512) {
        int k = i >> 7, n = i & 127;
        sW[k * LDTE + n] = __float2half(W[i]);
    }
    if (tid < HID) sbb[tid] = b[tid];
    __syncthreads();

    const int qlane = lane & 3;
    const int rlane = lane >> 2;
    const int ntiles = (N_EDGES + 127) / 128;

    for (int tile = blockIdx.x; tile < ntiles; tile += gridDim.x) {
        int e0 = tile * 128;
        // load A tile (eattr fp32 -> fp16), rows 32B each, contiguous block
        for (int i = tid; i < 128 * EDGE_DIM; i += 512) {
            int r = i >> 4, c = i & 15;
            int e = e0 + r;
            float v = (e < N_EDGES) ? eattr[(size_t)e * EDGE_DIM + c] : 0.f;
            sA[r * LDA + c] = __float2half(v);
        }
        // csr_fill for this tile
        if (tid < 128) {
            int e = e0 + tid;
            int slot = -1;
            if (e < N_EDGES) {
                int src = eidx[e];
                int dst = eidx[N_EDGES + e];
                slot = atomicAdd(&g_cur[dst], 1);
                g_csr_src[slot] = src;
            }
            sslot[tid] = slot;
        }
        __syncthreads();

        float acc[2][4][4];
        #pragma unroll
        for (int mb = 0; mb < 2; mb++)
            #pragma unroll
            for (int nb = 0; nb < 4; nb++)
                #pragma unroll
                for (int j = 0; j < 4; j++) acc[mb][nb][j] = 0.f;

        unsigned a[2][4];
        #pragma unroll
        for (int mb = 0; mb < 2; mb++) {
            int row = wr * 32 + mb * 16 + (lane & 15);
            unsigned addr = smem_u32(&sA[row * LDA + ((lane >> 4) << 3)]);
            ldsm_x4(addr, a[mb][0], a[mb][1], a[mb][2], a[mb][3]);
        }
        unsigned bf[4][2];
        #pragma unroll
        for (int np = 0; np < 2; np++) {
            int krow = lane & 15;
            int n0 = wc * 32 + np * 16 + ((lane >> 4) << 3);
            unsigned addr = smem_u32(&sW[krow * LDTE + n0]);
            unsigned r0, r1, r2, r3;
            ldsm_x4_t(addr, r0, r1, r2, r3);
            bf[2 * np][0] = r0; bf[2 * np][1] = r1;
            bf[2 * np + 1][0] = r2; bf[2 * np + 1][1] = r3;
        }
        #pragma unroll
        for (int mb = 0; mb < 2; mb++)
            #pragma unroll
            for (int nb = 0; nb < 4; nb++)
                mma16816(acc[mb][nb][0], acc[mb][nb][1], acc[mb][nb][2], acc[mb][nb][3],
                         a[mb][0], a[mb][1], a[mb][2], a[mb][3], bf[nb][0], bf[nb][1]);

        // epilogue: bias + scatter fp16 rows to CSR slots
        #pragma unroll
        for (int mb = 0; mb < 2; mb++) {
            #pragma unroll
            for (int nb = 0; nb < 4; nb++) {
                int col = wc * 32 + nb * 8 + 2 * qlane;
                float bx = sbb[col], by = sbb[col + 1];
                int r0i = wr * 32 + mb * 16 + rlane;
                int s0 = sslot[r0i];
                if (s0 >= 0)
                    *reinterpret_cast<__half2*>(&g_ea_h[(size_t)s0 * HID + col]) =
                        __floats2half2_rn(acc[mb][nb][0] + bx, acc[mb][nb][1] + by);
                int s1 = sslot[r0i + 8];
                if (s1 >= 0)
                    *reinterpret_cast<__half2*>(&g_ea_h[(size_t)s1 * HID + col]) =
                        __floats2half2_rn(acc[mb][nb][2] + bx, acc[mb][nb][3] + by);
            }
        }
        __syncthreads();
    }
}

// ---------------- node encoder: z16 = x @ node_w + node_b -------------------
__global__ void encoder_kernel(const float* __restrict__ x,
                               const float* __restrict__ W,
                               const float* __restrict__ b) {
    __shared__ float sW[NODE_DIM * HID];
    for (int i = threadIdx.x; i < NODE_DIM * HID; i += blockDim.x) sW[i] = W[i];
    __syncthreads();
    int lane = threadIdx.x & 31;
    int warp = (blockIdx.x * blockDim.x + threadIdx.x) >> 5;
    int nw = (gridDim.x * blockDim.x) >> 5;
    float4 bb = reinterpret_cast<const float4*>(b)[lane];
    for (int n = warp; n < N_NODES; n += nw) {
        const float4* xr = reinterpret_cast<const float4*>(x + (size_t)n * NODE_DIM);
        float4 acc = bb;
        #pragma unroll
        for (int kk = 0; kk < NODE_DIM / 4; kk++) {
            float4 xv = xr[kk];
            float xa[4] = {xv.x, xv.y, xv.z, xv.w};
            #pragma unroll
            for (int j = 0; j < 4; j++) {
                float4 w = *reinterpret_cast<const float4*>(&sW[(4 * kk + j) * HID + 4 * lane]);
                acc.x += xa[j] * w.x;
                acc.y += xa[j] * w.y;
                acc.z += xa[j] * w.z;
                acc.w += xa[j] * w.w;
            }
        }
        h16_store4(g_z16 + (size_t)n * HID + 4 * lane, acc);
    }
}

// ---- bn_apply: z16 <- relu(bn(z16)) in place (layers 0..NLAYERS-2) ---------
__global__ void bn_apply_kernel(const float* __restrict__ gamma,
                                const float* __restrict__ beta,
                                const float* __restrict__ stats) {
    int i = blockIdx.x * blockDim.x + threadIdx.x;
    const int n4 = N_NODES * HID / 4;
    if (i >= n4) return;
    int c0 = (i & 31) * 4;
    float4 z = h16_load4(g_z16 + (size_t)i * 4);
    float za[4] = {z.x, z.y, z.z, z.w};
    float out[4];
    const float invN = 1.0f / (float)N_NODES;
    #pragma unroll
    for (int j = 0; j < 4; j++) {
        int c = c0 + j;
        float mean = stats[c] * invN;
        float var = stats[HID + c] * invN - mean * mean;
        float rstd = rsqrtf(var + BN_EPS);
        float o = gamma[c] * (za[j] - mean) * rstd + beta[c];
        out[j] = fmaxf(o, 0.f);
    }
    h16_store4(g_z16 + (size_t)i * 4, make_float4(out[0], out[1], out[2], out[3]));
}

// ---- aggregation (BN-free): zin[n] = h[n] + sum_{e->n} relu(h[src]+ea[e]) --
// x8 unroll: 16 independent 256B loads in flight per warp.
#define ACCUM1(H, E) do { \
    float4 hh = u2_to_f4(H), ee = u2_to_f4(E); \
    acc.x += fmaxf(hh.x + ee.x, 0.f); \
    acc.y += fmaxf(hh.y + ee.y, 0.f); \
    acc.z += fmaxf(hh.z + ee.z, 0.f); \
    acc.w += fmaxf(hh.w + ee.w, 0.f); \
} while (0)

__global__ __launch_bounds__(256, 4)
void agg_kernel() {
    int lane = threadIdx.x & 31;
    int warp = (blockIdx.x * blockDim.x + threadIdx.x) >> 5;
    int nw = (gridDim.x * blockDim.x) >> 5;
    const __half* zp = g_z16;
    const __half* ep = g_ea_h;
    const int col = 4 * lane;

    for (int n = warp; n < N_NODES; n += nw) {
        float4 acc = u2_to_f4(*reinterpret_cast<const uint2*>(zp + (size_t)n * HID + col));
        int s = __ldg(&g_off[n]);
        int e = __ldg(&g_off[n + 1]);
        int idx = s;
        for (; idx + 8 <= e; idx += 8) {
            int s0 = __ldg(&g_csr_src[idx]);
            int s1 = __ldg(&g_csr_src[idx + 1]);
            int s2 = __ldg(&g_csr_src[idx + 2]);
            int s3 = __ldg(&g_csr_src[idx + 3]);
            int s4 = __ldg(&g_csr_src[idx + 4]);
            int s5 = __ldg(&g_csr_src[idx + 5]);
            int s6 = __ldg(&g_csr_src[idx + 6]);
            int s7 = __ldg(&g_csr_src[idx + 7]);
            uint2 H0 = *reinterpret_cast<const uint2*>(zp + (size_t)s0 * HID + col);
            uint2 H1 = *reinterpret_cast<const uint2*>(zp + (size_t)s1 * HID + col);
            uint2 H2 = *reinterpret_cast<const uint2*>(zp + (size_t)s2 * HID + col);
            uint2 H3 = *reinterpret_cast<const uint2*>(zp + (size_t)s3 * HID + col);
            uint2 H4 = *reinterpret_cast<const uint2*>(zp + (size_t)s4 * HID + col);
            uint2 H5 = *reinterpret_cast<const uint2*>(zp + (size_t)s5 * HID + col);
            uint2 H6 = *reinterpret_cast<const uint2*>(zp + (size_t)s6 * HID + col);
            uint2 H7 = *reinterpret_cast<const uint2*>(zp + (size_t)s7 * HID + col);
            uint2 E0 = *reinterpret_cast<const uint2*>(ep + (size_t)(idx + 0) * HID + col);
            uint2 E1 = *reinterpret_cast<const uint2*>(ep + (size_t)(idx + 1) * HID + col);
            uint2 E2 = *reinterpret_cast<const uint2*>(ep + (size_t)(idx + 2) * HID + col);
            uint2 E3 = *reinterpret_cast<const uint2*>(ep + (size_t)(idx + 3) * HID + col);
            uint2 E4 = *reinterpret_cast<const uint2*>(ep + (size_t)(idx + 4) * HID + col);
            uint2 E5 = *reinterpret_cast<const uint2*>(ep + (size_t)(idx + 5) * HID + col);
            uint2 E6 = *reinterpret_cast<const uint2*>(ep + (size_t)(idx + 6) * HID + col);
            uint2 E7 = *reinterpret_cast<const uint2*>(ep + (size_t)(idx + 7) * HID + col);
            ACCUM1(H0, E0); ACCUM1(H1, E1); ACCUM1(H2, E2); ACCUM1(H3, E3);
            ACCUM1(H4, E4); ACCUM1(H5, E5); ACCUM1(H6, E6); ACCUM1(H7, E7);
        }
        if (idx + 4 <= e) {
            int s0 = __ldg(&g_csr_src[idx]);
            int s1 = __ldg(&g_csr_src[idx + 1]);
            int s2 = __ldg(&g_csr_src[idx + 2]);
            int s3 = __ldg(&g_csr_src[idx + 3]);
            uint2 H0 = *reinterpret_cast<const uint2*>(zp + (size_t)s0 * HID + col);
            uint2 H1 = *reinterpret_cast<const uint2*>(zp + (size_t)s1 * HID + col);
            uint2 H2 = *reinterpret_cast<const uint2*>(zp + (size_t)s2 * HID + col);
            uint2 H3 = *reinterpret_cast<const uint2*>(zp + (size_t)s3 * HID + col);
            uint2 E0 = *reinterpret_cast<const uint2*>(ep + (size_t)(idx + 0) * HID + col);
            uint2 E1 = *reinterpret_cast<const uint2*>(ep + (size_t)(idx + 1) * HID + col);
            uint2 E2 = *reinterpret_cast<const uint2*>(ep + (size_t)(idx + 2) * HID + col);
            uint2 E3 = *reinterpret_cast<const uint2*>(ep + (size_t)(idx + 3) * HID + col);
            ACCUM1(H0, E0); ACCUM1(H1, E1); ACCUM1(H2, E2); ACCUM1(H3, E3);
            idx += 4;
        }
        if (idx + 2 <= e) {
            int s0 = __ldg(&g_csr_src[idx]);
            int s1 = __ldg(&g_csr_src[idx + 1]);
            uint2 H0 = *reinterpret_cast<const uint2*>(zp + (size_t)s0 * HID + col);
            uint2 H1 = *reinterpret_cast<const uint2*>(zp + (size_t)s1 * HID + col);
            uint2 E0 = *reinterpret_cast<const uint2*>(ep + (size_t)(idx + 0) * HID + col);
            uint2 E1 = *reinterpret_cast<const uint2*>(ep + (size_t)(idx + 1) * HID + col);
            ACCUM1(H0, E0); ACCUM1(H1, E1);
            idx += 2;
        }
        if (idx < e) {
            int s0 = __ldg(&g_csr_src[idx]);
            uint2 H0 = *reinterpret_cast<const uint2*>(zp + (size_t)s0 * HID + col);
            uint2 E0 = *reinterpret_cast<const uint2*>(ep + (size_t)idx * HID + col);
            ACCUM1(H0, E0);
        }
        h16_store4(g_zin16 + (size_t)n * HID + col, acc);
    }
}

// ---------------- MLP via tensor cores (mma.sync m16n8k16) ------------------
#define LDT 136
#define MLP_SMEM_BYTES (4 * HID * LDT * 2 + 2 * HID * 4)
__global__ __launch_bounds__(512, 1)
void mlp_mma_kernel(const __half* __restrict__ W16,
                    const float* __restrict__ B1, const float* __restrict__ B2,
                    float* __restrict__ stats) {
    extern __shared__ __half smh[];
    __half* sW1 = smh;
    __half* sW2 = sW1 + HID * LDT;
    __half* sIn = sW2 + HID * LDT;
    __half* sT  = sIn + HID * LDT;
    float* sB1 = (float*)(sT + HID * LDT);
    float* sB2 = sB1 + HID;

    int tid = threadIdx.x;
    int lane = tid & 31;
    int wid = tid >> 5;
    int wr = wid >> 2;
    int wc = wid & 3;

    for (int i = tid; i < HID * HID; i += 512) {
        int r = i >> 7, c = i & 127;
        sW1[r * LDT + c] = W16[i];
        sW2[r * LDT + c] = W16[HID * HID + i];
    }
    if (tid < HID) { sB1[tid] = B1[tid]; sB2[tid] = B2[tid]; }
    __syncthreads();

    int rpb = (N_NODES + gridDim.x - 1) / gridDim.x;
    int base = blockIdx.x * rpb;
    int rend = min(base + rpb, N_NODES);

    float ls[8], lss[8];
    #pragma unroll
    for (int j = 0; j < 8; j++) { ls[j] = 0.f; lss[j] = 0.f; }

    const int qlane = lane & 3;
    const int rlane = lane >> 2;

    for (int rbase = base; rbase < rend; rbase += HID) {
        for (int i = tid; i < HID * 16; i += 512) {
            int r = i >> 4, q = i & 15;
            int row = rbase + r;
            uint4 v = make_uint4(0u, 0u, 0u, 0u);
            if (row < rend) v = *reinterpret_cast<const uint4*>(g_zin16 + (size_t)row * HID + q * 8);
            *reinterpret_cast<uint4*>(&sIn[r * LDT + q * 8]) = v;
        }
        __syncthreads();

        float acc[2][4][4];
        #pragma unroll
        for (int mb = 0; mb < 2; mb++)
            #pragma unroll
            for (int nb = 0; nb < 4; nb++)
                #pragma unroll
                for (int j = 0; j < 4; j++) acc[mb][nb][j] = 0.f;

        #pragma unroll
        for (int ks = 0; ks < 8; ks++) {
            int k0 = ks * 16;
            unsigned a[2][4];
            #pragma unroll
            for (int mb = 0; mb < 2; mb++) {
                int row = wr * 32 + mb * 16 + (lane & 15);
                unsigned addr = smem_u32(&sIn[row * LDT + k0 + ((lane >> 4) << 3)]);
                ldsm_x4(addr, a[mb][0], a[mb][1], a[mb][2], a[mb][3]);
            }
            unsigned b[4][2];
            #pragma unroll
            for (int np = 0; np < 2; np++) {
                int krow = k0 + (lane & 15);
                int n0 = wc * 32 + np * 16 + ((lane >> 4) << 3);
                unsigned addr = smem_u32(&sW1[krow * LDT + n0]);
                unsigned r0, r1, r2, r3;
                ldsm_x4_t(addr, r0, r1, r2, r3);
                b[2 * np][0] = r0; b[2 * np][1] = r1;
                b[2 * np + 1][0] = r2; b[2 * np + 1][1] = r3;
            }
            #pragma unroll
            for (int mb = 0; mb < 2; mb++)
                #pragma unroll
                for (int nb = 0; nb < 4; nb++)
                    mma16816(acc[mb][nb][0], acc[mb][nb][1], acc[mb][nb][2], acc[mb][nb][3],
                             a[mb][0], a[mb][1], a[mb][2], a[mb][3], b[nb][0], b[nb][1]);
        }
        __syncthreads();
        #pragma unroll
        for (int mb = 0; mb < 2; mb++) {
            #pragma unroll
            for (int nb = 0; nb < 4; nb++) {
                int col = wc * 32 + nb * 8 + 2 * qlane;
                float bx = sB1[col], by = sB1[col + 1];
                int rlo = wr * 32 + mb * 16 + rlane;
                *reinterpret_cast<__half2*>(&sT[rlo * LDT + col]) =
                    __floats2half2_rn(fmaxf(acc[mb][nb][0] + bx, 0.f),
                                      fmaxf(acc[mb][nb][1] + by, 0.f));
                *reinterpret_cast<__half2*>(&sT[(rlo + 8) * LDT + col]) =
                    __floats2half2_rn(fmaxf(acc[mb][nb][2] + bx, 0.f),
                                      fmaxf(acc[mb][nb][3] + by, 0.f));
            }
        }
        __syncthreads();

        #pragma unroll
        for (int mb = 0; mb < 2; mb++)
            #pragma unroll
            for (int nb = 0; nb < 4; nb++)
                #pragma unroll
                for (int j = 0; j < 4; j++) acc[mb][nb][j] = 0.f;

        #pragma unroll
        for (int ks = 0; ks < 8; ks++) {
            int k0 = ks * 16;
            unsigned a[2][4];
            #pragma unroll
            for (int mb = 0; mb < 2; mb++) {
                int row = wr * 32 + mb * 16 + (lane & 15);
                unsigned addr = smem_u32(&sT[row * LDT + k0 + ((lane >> 4) << 3)]);
                ldsm_x4(addr, a[mb][0], a[mb][1], a[mb][2], a[mb][3]);
            }
            unsigned b[4][2];
            #pragma unroll
            for (int np = 0; np < 2; np++) {
                int krow = k0 + (lane & 15);
                int n0 = wc * 32 + np * 16 + ((lane >> 4) << 3);
                unsigned addr = smem_u32(&sW2[krow * LDT + n0]);
                unsigned r0, r1, r2, r3;
                ldsm_x4_t(addr, r0, r1, r2, r3);
                b[2 * np][0] = r0; b[2 * np][1] = r1;
                b[2 * np + 1][0] = r2; b[2 * np + 1][1] = r3;
            }
            #pragma unroll
            for (int mb = 0; mb < 2; mb++)
                #pragma unroll
                for (int nb = 0; nb < 4; nb++)
                    mma16816(acc[mb][nb][0], acc[mb][nb][1], acc[mb][nb][2], acc[mb][nb][3],
                             a[mb][0], a[mb][1], a[mb][2], a[mb][3], b[nb][0], b[nb][1]);
        }
        #pragma unroll
        for (int mb = 0; mb < 2; mb++) {
            #pragma unroll
            for (int nb = 0; nb < 4; nb++) {
                int col = wc * 32 + nb * 8 + 2 * qlane;
                float bx = sB2[col], by = sB2[col + 1];
                int rlo = rbase + wr * 32 + mb * 16 + rlane;
                float z0 = acc[mb][nb][0] + bx, z1 = acc[mb][nb][1] + by;
                float z2 = acc[mb][nb][2] + bx, z3 = acc[mb][nb][3] + by;
                if (rlo < rend) {
                    *reinterpret_cast<__half2*>(&g_z16[(size_t)rlo * HID + col]) =
                        __floats2half2_rn(z0, z1);
                    ls[2 * nb] += z0; lss[2 * nb] += z0 * z0;
                    ls[2 * nb + 1] += z1; lss[2 * nb + 1] += z1 * z1;
                }
                if (rlo + 8 < rend) {
                    *reinterpret_cast<__half2*>(&g_z16[(size_t)(rlo + 8) * HID + col]) =
                        __floats2half2_rn(z2, z3);
                    ls[2 * nb] += z2; lss[2 * nb] += z2 * z2;
                    ls[2 * nb + 1] += z3; lss[2 * nb + 1] += z3 * z3;
                }
            }
        }
        __syncthreads();
    }

    #pragma unroll
    for (int j = 0; j < 8; j++) {
        #pragma unroll
        for (int o = 4; o < 32; o <<= 1) {
            ls[j]  += __shfl_xor_sync(0xffffffffu, ls[j], o);
            lss[j] += __shfl_xor_sync(0xffffffffu, lss[j], o);
        }
    }
    if (lane < 4) {
        #pragma unroll
        for (int nb = 0; nb < 4; nb++) {
            #pragma unroll
            for (int j = 0; j < 2; j++) {
                int col = wc * 32 + nb * 8 + 2 * lane + j;
                atomicAdd(&stats[col], ls[2 * nb + j]);
                atomicAdd(&stats[HID + col], lss[2 * nb + j]);
            }
        }
    }
}

// ---------------- last layer: BN + relu + pool (reads z16) ------------------
__global__ void bn_pool_kernel(const float* __restrict__ gamma,
                               const float* __restrict__ beta,
                               const float* __restrict__ stats,
                               const int* __restrict__ batch) {
    int i = blockIdx.x * blockDim.x + threadIdx.x;
    const int n4 = N_NODES * HID / 4;
    if (i >= n4) return;
    int n = i >> 5;
    int c0 = (i & 31) * 4;
    float4 z = h16_load4(g_z16 + (size_t)i * 4);
    float za[4] = {z.x, z.y, z.z, z.w};
    float out[4];
    const float invN = 1.0f / (float)N_NODES;
    #pragma unroll
    for (int j = 0; j < 4; j++) {
        int c = c0 + j;
        float mean = stats[c] * invN;
        float var = stats[HID + c] * invN - mean * mean;
        float rstd = rsqrtf(var + BN_EPS);
        float o = gamma[c] * (za[j] - mean) * rstd + beta[c];
        out[j] = fmaxf(o, 0.f);
    }
    int gi = __ldg(&batch[n]);
    red_add_v4(g_pool + (size_t)gi * HID + c0,
               make_float4(out[0], out[1], out[2], out[3]));
}

// ---------------- head: out = relu(g@W1+b1)@W2+b2 ---------------------------
__global__ void head_kernel(const float* __restrict__ w1, const float* __restrict__ b1,
                            const float* __restrict__ w2, const float* __restrict__ b2,
                            float* __restrict__ out) {
    __shared__ float srow[HID];
    __shared__ float st[HID];
    int gi = blockIdx.x;
    int c = threadIdx.x;
    srow[c] = g_pool[(size_t)gi * HID + c];
    __syncthreads();
    float acc = b1[c];
    for (int k = 0; k < HID; k++) acc += srow[k] * w1[k * HID + c];
    st[c] = fmaxf(acc, 0.f);
    __syncthreads();
    if (c < 2) {
        float o = b2[c];
        for (int k = 0; k < HID; k++) o += st[k] * w2[k * 2 + c];
        out[gi * 2 + c] = o;
    }
}

// ---------------- launch -----------------------------------------------------
extern "C" void kernel_launch(void* const* d_in, const int* in_sizes, int n_in,
                              void* d_out, int out_size) {
    const float* x        = (const float*)d_in[0];
    const int*   eidx     = (const int*)d_in[1];
    const float* eattr    = (const float*)d_in[2];
    const int*   batch    = (const int*)d_in[3];
    const float* node_w   = (const float*)d_in[4];
    const float* node_b   = (const float*)d_in[5];
    const float* edge_w   = (const float*)d_in[6];
    const float* edge_b   = (const float*)d_in[7];
    const float* mlp_w1   = (const float*)d_in[8];
    const float* mlp_b1   = (const float*)d_in[9];
    const float* mlp_w2   = (const float*)d_in[10];
    const float* mlp_b2   = (const float*)d_in[11];
    const float* bn_gamma = (const float*)d_in[12];
    const float* bn_beta  = (const float*)d_in[13];
    const float* head_w1  = (const float*)d_in[14];
    const float* head_b1  = (const float*)d_in[15];
    const float* head_w2  = (const float*)d_in[16];
    const float* head_b2  = (const float*)d_in[17];
    float* out = (float*)d_out;

    cudaFuncSetAttribute(mlp_mma_kernel, cudaFuncAttributeMaxDynamicSharedMemorySize,
                         MLP_SMEM_BYTES);

    float* d_stats;
    cudaGetSymbolAddress((void**)&d_stats, g_stats);
    __half* d_w16;
    cudaGetSymbolAddress((void**)&d_w16, g_w16);

    convert_w_kernel<<<(2 * NLAYERS * HID * HID + 255) / 256, 256>>>(mlp_w1, mlp_w2);
    csr_count_kernel<<<(N_EDGES + 255) / 256, 256>>>(eidx);
    chunk_sum_kernel<<<NCHUNK / 128, 128>>>();
    chunk_scan_kernel<<<1, NCHUNK>>>();
    chunk_offs_kernel<<<NCHUNK / 128, 128>>>();
    edge_enc_mma_kernel<<<592, 512>>>(eattr, eidx, edge_w, edge_b);
    encoder_kernel<<<512, 256>>>(x, node_w, node_b);

    const int grid_elem = (N_NODES * HID / 4 + 255) / 256;
    for (int l = 0; l < NLAYERS; l++) {
        agg_kernel<<<4096, 256>>>();
        mlp_mma_kernel<<<148, 512, MLP_SMEM_BYTES>>>(
            d_w16 + (size_t)l * 2 * HID * HID,
            mlp_b1 + (size_t)l * HID,
            mlp_b2 + (size_t)l * HID,
            d_stats + (size_t)l * 2 * HID);
        if (l < NLAYERS - 1) {
            bn_apply_kernel<<<grid_elem, 256>>>(bn_gamma + (size_t)l * HID,
                                                bn_beta + (size_t)l * HID,
                                                d_stats + (size_t)l * 2 * HID);
        }
    }

    bn_pool_kernel<<<grid_elem, 256>>>(
        bn_gamma + (size_t)(NLAYERS - 1) * HID,
        bn_beta + (size_t)(NLAYERS - 1) * HID,
        d_stats + (size_t)(NLAYERS - 1) * 2 * HID, batch);
    head_kernel<<<NGRAPHS, HID>>>(head_w1, head_b1, head_w2, head_b2, out);
}

// round 15
// speedup vs baseline: 1.3606x; 1.0286x over previous
#include <cuda_runtime.h>
#include <cuda_fp16.h>

#define N_NODES 50000
#define N_EDGES 600000
#define HID 128
#define NODE_DIM 64
#define EDGE_DIM 16
#define NLAYERS 3
#define NGRAPHS 256
#define BN_EPS 1e-5f

typedef unsigned long long u64;

// ---------------- scratch (device globals; no allocations allowed) ----------
__device__ __half g_z16[N_NODES * HID];    // node features (post bn_apply) / pre-BN z
__device__ __half g_zin16[N_NODES * HID];  // h + agg (MLP input), fp16
__device__ __half g_ea_h[N_EDGES * HID];   // encoded edge features, fp16, CSR order
__device__ __half g_w16[NLAYERS * 2 * HID * HID];  // fp16 MLP weights
__device__ float g_stats[NLAYERS * 2 * HID]; // per-layer column sums / sumsq
__device__ float g_pool[NGRAPHS * HID];    // pooled graph features
// CSR by destination
__device__ int g_cnt[N_NODES];
__device__ int g_off[N_NODES + 1];
__device__ int g_cur[N_NODES];
__device__ int g_csr_src[N_EDGES];
// parallel scan scratch
#define NCHUNK 1024
#define CHSZ ((N_NODES + NCHUNK - 1) / NCHUNK)
__device__ int g_chunk[NCHUNK];
__device__ int g_chunk_base[NCHUNK];

// ---------------- helpers ----------------------------------------------------
__device__ __forceinline__ void red_add_v4(float* p, float4 v) {
    asm volatile("red.global.add.v4.f32 [%0], {%1,%2,%3,%4};"
                 :: "l"(p), "f"(v.x), "f"(v.y), "f"(v.z), "f"(v.w) : "memory");
}

__device__ __forceinline__ float4 h16_load4(const __half* p) {
    uint2 u = *reinterpret_cast<const uint2*>(p);
    __half2 a = *reinterpret_cast<__half2*>(&u.x);
    __half2 b = *reinterpret_cast<__half2*>(&u.y);
    float2 fa = __half22float2(a);
    float2 fb = __half22float2(b);
    return make_float4(fa.x, fa.y, fb.x, fb.y);
}
__device__ __forceinline__ float4 u2_to_f4(uint2 u) {
    __half2 a = *reinterpret_cast<__half2*>(&u.x);
    __half2 b = *reinterpret_cast<__half2*>(&u.y);
    float2 fa = __half22float2(a);
    float2 fb = __half22float2(b);
    return make_float4(fa.x, fa.y, fb.x, fb.y);
}
__device__ __forceinline__ void h16_store4(__half* p, float4 v) {
    union { __half2 h[2]; uint2 u; } cv;
    cv.h[0] = __floats2half2_rn(v.x, v.y);
    cv.h[1] = __floats2half2_rn(v.z, v.w);
    *reinterpret_cast<uint2*>(p) = cv.u;
}

__device__ __forceinline__ unsigned smem_u32(const void* p) {
    return (unsigned)__cvta_generic_to_shared(p);
}
__device__ __forceinline__ void ldsm_x4(unsigned addr, unsigned& r0, unsigned& r1,
                                        unsigned& r2, unsigned& r3) {
    asm volatile("ldmatrix.sync.aligned.m8n8.x4.shared.b16 {%0,%1,%2,%3},[%4];"
                 : "=r"(r0), "=r"(r1), "=r"(r2), "=r"(r3) : "r"(addr));
}
__device__ __forceinline__ void ldsm_x4_t(unsigned addr, unsigned& r0, unsigned& r1,
                                          unsigned& r2, unsigned& r3) {
    asm volatile("ldmatrix.sync.aligned.m8n8.x4.trans.shared.b16 {%0,%1,%2,%3},[%4];"
                 : "=r"(r0), "=r"(r1), "=r"(r2), "=r"(r3) : "r"(addr));
}
__device__ __forceinline__ void mma16816(float& c0, float& c1, float& c2, float& c3,
                                         unsigned a0, unsigned a1, unsigned a2, unsigned a3,
                                         unsigned b0, unsigned b1) {
    asm volatile("mma.sync.aligned.m16n8k16.row.col.f32.f16.f16.f32 "
                 "{%0,%1,%2,%3},{%4,%5,%6,%7},{%8,%9},{%0,%1,%2,%3};"
                 : "+f"(c0), "+f"(c1), "+f"(c2), "+f"(c3)
                 : "r"(a0), "r"(a1), "r"(a2), "r"(a3), "r"(b0), "r"(b1));
}

// ---------------- weight conversion + zeroing (launch 0) --------------------
__global__ void convert_w_kernel(const float* __restrict__ w1,
                                 const float* __restrict__ w2) {
    int gt = blockIdx.x * blockDim.x + threadIdx.x;
    int gsz = gridDim.x * blockDim.x;
    for (int i = gt; i < N_NODES; i += gsz) g_cnt[i] = 0;
    for (int i = gt; i < NGRAPHS * HID; i += gsz) g_pool[i] = 0.f;
    for (int i = gt; i < NLAYERS * 2 * HID; i += gsz) g_stats[i] = 0.f;

    int i = gt;
    const int per = NLAYERS * HID * HID;
    if (i < per) {
        int l = i / (HID * HID);
        int j = i % (HID * HID);
        g_w16[(size_t)l * 2 * HID * HID + j] = __float2half(w1[i]);
    } else if (i < 2 * per) {
        int k = i - per;
        int l = k / (HID * HID);
        int j = k % (HID * HID);
        g_w16[(size_t)l * 2 * HID * HID + HID * HID + j] = __float2half(w2[k]);
    }
}

// ---------------- CSR build --------------------------------------------------
__global__ void csr_count_kernel(const int* __restrict__ eidx) {
    int e = blockIdx.x * blockDim.x + threadIdx.x;
    if (e < N_EDGES) atomicAdd(&g_cnt[eidx[N_EDGES + e]], 1);
}

__global__ void chunk_sum_kernel() {
    int t = blockIdx.x * blockDim.x + threadIdx.x;
    if (t >= NCHUNK) return;
    int beg = t * CHSZ;
    int end = min(beg + CHSZ, N_NODES);
    int s = 0;
    for (int i = beg; i < end; i++) s += g_cnt[i];
    g_chunk[t] = s;
}

__global__ void chunk_scan_kernel() {
    __shared__ int ssum[NCHUNK];
    int t = threadIdx.x;
    ssum[t] = g_chunk[t];
    __syncthreads();
    for (int off = 1; off < NCHUNK; off <<= 1) {
        int v = (t >= off) ? ssum[t - off] : 0;
        __syncthreads();
        ssum[t] += v;
        __syncthreads();
    }
    g_chunk_base[t] = (t == 0) ? 0 : ssum[t - 1];
    if (t == NCHUNK - 1) g_off[N_NODES] = ssum[t];
}

__global__ void chunk_offs_kernel() {
    int t = blockIdx.x * blockDim.x + threadIdx.x;
    if (t >= NCHUNK) return;
    int beg = t * CHSZ;
    int end = min(beg + CHSZ, N_NODES);
    int run = g_chunk_base[t];
    for (int i = beg; i < end; i++) {
        g_off[i] = run;
        g_cur[i] = run;
        run += g_cnt[i];
    }
}

// --- edge encoder via tensor cores + fused csr_fill --------------------------
#define LDTE 136   // sW row stride (halves)
#define LDA 24     // sA row stride (halves)
__global__ __launch_bounds__(512)
void edge_enc_mma_kernel(const float* __restrict__ eattr,
                         const int* __restrict__ eidx,
                         const float* __restrict__ W,
                         const float* __restrict__ b) {
    __shared__ __half sW[EDGE_DIM * LDTE];
    __shared__ __half sA[128 * LDA];
    __shared__ float sbb[HID];
    __shared__ int sslot[128];

    int tid = threadIdx.x;
    int lane = tid & 31;
    int wid = tid >> 5;
    int wr = wid >> 2;
    int wc = wid & 3;

    for (int i = tid; i < EDGE_DIM * HID; i += 512) {
        int k = i >> 7, n = i & 127;
        sW[k * LDTE + n] = __float2half(W[i]);
    }
    if (tid < HID) sbb[tid] = b[tid];
    __syncthreads();

    const int qlane = lane & 3;
    const int rlane = lane >> 2;
    const int ntiles = (N_EDGES + 127) / 128;

    for (int tile = blockIdx.x; tile < ntiles; tile += gridDim.x) {
        int e0 = tile * 128;
        for (int i = tid; i < 128 * EDGE_DIM; i += 512) {
            int r = i >> 4, c = i & 15;
            int e = e0 + r;
            float v = (e < N_EDGES) ? eattr[(size_t)e * EDGE_DIM + c] : 0.f;
            sA[r * LDA + c] = __float2half(v);
        }
        if (tid < 128) {
            int e = e0 + tid;
            int slot = -1;
            if (e < N_EDGES) {
                int src = eidx[e];
                int dst = eidx[N_EDGES + e];
                slot = atomicAdd(&g_cur[dst], 1);
                g_csr_src[slot] = src;
            }
            sslot[tid] = slot;
        }
        __syncthreads();

        float acc[2][4][4];
        #pragma unroll
        for (int mb = 0; mb < 2; mb++)
            #pragma unroll
            for (int nb = 0; nb < 4; nb++)
                #pragma unroll
                for (int j = 0; j < 4; j++) acc[mb][nb][j] = 0.f;

        unsigned a[2][4];
        #pragma unroll
        for (int mb = 0; mb < 2; mb++) {
            int row = wr * 32 + mb * 16 + (lane & 15);
            unsigned addr = smem_u32(&sA[row * LDA + ((lane >> 4) << 3)]);
            ldsm_x4(addr, a[mb][0], a[mb][1], a[mb][2], a[mb][3]);
        }
        unsigned bf[4][2];
        #pragma unroll
        for (int np = 0; np < 2; np++) {
            int krow = lane & 15;
            int n0 = wc * 32 + np * 16 + ((lane >> 4) << 3);
            unsigned addr = smem_u32(&sW[krow * LDTE + n0]);
            unsigned r0, r1, r2, r3;
            ldsm_x4_t(addr, r0, r1, r2, r3);
            bf[2 * np][0] = r0; bf[2 * np][1] = r1;
            bf[2 * np + 1][0] = r2; bf[2 * np + 1][1] = r3;
        }
        #pragma unroll
        for (int mb = 0; mb < 2; mb++)
            #pragma unroll
            for (int nb = 0; nb < 4; nb++)
                mma16816(acc[mb][nb][0], acc[mb][nb][1], acc[mb][nb][2], acc[mb][nb][3],
                         a[mb][0], a[mb][1], a[mb][2], a[mb][3], bf[nb][0], bf[nb][1]);

        #pragma unroll
        for (int mb = 0; mb < 2; mb++) {
            #pragma unroll
            for (int nb = 0; nb < 4; nb++) {
                int col = wc * 32 + nb * 8 + 2 * qlane;
                float bx = sbb[col], by = sbb[col + 1];
                int r0i = wr * 32 + mb * 16 + rlane;
                int s0 = sslot[r0i];
                if (s0 >= 0)
                    *reinterpret_cast<__half2*>(&g_ea_h[(size_t)s0 * HID + col]) =
                        __floats2half2_rn(acc[mb][nb][0] + bx, acc[mb][nb][1] + by);
                int s1 = sslot[r0i + 8];
                if (s1 >= 0)
                    *reinterpret_cast<__half2*>(&g_ea_h[(size_t)s1 * HID + col]) =
                        __floats2half2_rn(acc[mb][nb][2] + bx, acc[mb][nb][3] + by);
            }
        }
        __syncthreads();
    }
}

// ---------------- node encoder: z16 = x @ node_w + node_b -------------------
__global__ void encoder_kernel(const float* __restrict__ x,
                               const float* __restrict__ W,
                               const float* __restrict__ b) {
    __shared__ float sW[NODE_DIM * HID];
    for (int i = threadIdx.x; i < NODE_DIM * HID; i += blockDim.x) sW[i] = W[i];
    __syncthreads();
    int lane = threadIdx.x & 31;
    int warp = (blockIdx.x * blockDim.x + threadIdx.x) >> 5;
    int nw = (gridDim.x * blockDim.x) >> 5;
    float4 bb = reinterpret_cast<const float4*>(b)[lane];
    for (int n = warp; n < N_NODES; n += nw) {
        const float4* xr = reinterpret_cast<const float4*>(x + (size_t)n * NODE_DIM);
        float4 acc = bb;
        #pragma unroll
        for (int kk = 0; kk < NODE_DIM / 4; kk++) {
            float4 xv = xr[kk];
            float xa[4] = {xv.x, xv.y, xv.z, xv.w};
            #pragma unroll
            for (int j = 0; j < 4; j++) {
                float4 w = *reinterpret_cast<const float4*>(&sW[(4 * kk + j) * HID + 4 * lane]);
                acc.x += xa[j] * w.x;
                acc.y += xa[j] * w.y;
                acc.z += xa[j] * w.z;
                acc.w += xa[j] * w.w;
            }
        }
        h16_store4(g_z16 + (size_t)n * HID + 4 * lane, acc);
    }
}

// ---- bn_apply: z16 <- relu(bn(z16)) in place (layers 0..NLAYERS-2) ---------
__global__ void bn_apply_kernel(const float* __restrict__ gamma,
                                const float* __restrict__ beta,
                                const float* __restrict__ stats) {
    int i = blockIdx.x * blockDim.x + threadIdx.x;
    const int n4 = N_NODES * HID / 4;
    if (i >= n4) return;
    int c0 = (i & 31) * 4;
    float4 z = h16_load4(g_z16 + (size_t)i * 4);
    float za[4] = {z.x, z.y, z.z, z.w};
    float out[4];
    const float invN = 1.0f / (float)N_NODES;
    #pragma unroll
    for (int j = 0; j < 4; j++) {
        int c = c0 + j;
        float mean = stats[c] * invN;
        float var = stats[HID + c] * invN - mean * mean;
        float rstd = rsqrtf(var + BN_EPS);
        float o = gamma[c] * (za[j] - mean) * rstd + beta[c];
        out[j] = fmaxf(o, 0.f);
    }
    h16_store4(g_z16 + (size_t)i * 4, make_float4(out[0], out[1], out[2], out[3]));
}

// ---- aggregation (BN-free, half2 message math) ------------------------------
// per edge-pair: HADD2/HMAX2 in fp16, ONE convert + float-accumulate per pair.
#define H2(u) (*reinterpret_cast<const __half2*>(&(u)))

#define ACCUM2H(Ha, Ea, Hb, Eb) do { \
    __half2 mlo = __hadd2(__hmax2(__hadd2(H2(Ha.x), H2(Ea.x)), z2), \
                          __hmax2(__hadd2(H2(Hb.x), H2(Eb.x)), z2)); \
    __half2 mhi = __hadd2(__hmax2(__hadd2(H2(Ha.y), H2(Ea.y)), z2), \
                          __hmax2(__hadd2(H2(Hb.y), H2(Eb.y)), z2)); \
    float2 f0 = __half22float2(mlo); \
    float2 f1 = __half22float2(mhi); \
    acc.x += f0.x; acc.y += f0.y; acc.z += f1.x; acc.w += f1.y; \
} while (0)

#define ACCUM1H(H, E) do { \
    __half2 mlo = __hmax2(__hadd2(H2(H.x), H2(E.x)), z2); \
    __half2 mhi = __hmax2(__hadd2(H2(H.y), H2(E.y)), z2); \
    float2 f0 = __half22float2(mlo); \
    float2 f1 = __half22float2(mhi); \
    acc.x += f0.x; acc.y += f0.y; acc.z += f1.x; acc.w += f1.y; \
} while (0)

__global__ __launch_bounds__(256, 4)
void agg_kernel() {
    int lane = threadIdx.x & 31;
    int warp = (blockIdx.x * blockDim.x + threadIdx.x) >> 5;
    int nw = (gridDim.x * blockDim.x) >> 5;
    const __half* zp = g_z16;
    const __half* ep = g_ea_h;
    const int col = 4 * lane;
    const __half2 z2 = __float2half2_rn(0.f);

    for (int n = warp; n < N_NODES; n += nw) {
        float4 acc = u2_to_f4(*reinterpret_cast<const uint2*>(zp + (size_t)n * HID + col));
        int s = __ldg(&g_off[n]);
        int e = __ldg(&g_off[n + 1]);
        int idx = s;
        for (; idx + 8 <= e; idx += 8) {
            int s0 = __ldg(&g_csr_src[idx]);
            int s1 = __ldg(&g_csr_src[idx + 1]);
            int s2 = __ldg(&g_csr_src[idx + 2]);
            int s3 = __ldg(&g_csr_src[idx + 3]);
            int s4 = __ldg(&g_csr_src[idx + 4]);
            int s5 = __ldg(&g_csr_src[idx + 5]);
            int s6 = __ldg(&g_csr_src[idx + 6]);
            int s7 = __ldg(&g_csr_src[idx + 7]);
            uint2 H0 = *reinterpret_cast<const uint2*>(zp + (size_t)s0 * HID + col);
            uint2 H1 = *reinterpret_cast<const uint2*>(zp + (size_t)s1 * HID + col);
            uint2 H2_ = *reinterpret_cast<const uint2*>(zp + (size_t)s2 * HID + col);
            uint2 H3 = *reinterpret_cast<const uint2*>(zp + (size_t)s3 * HID + col);
            uint2 H4 = *reinterpret_cast<const uint2*>(zp + (size_t)s4 * HID + col);
            uint2 H5 = *reinterpret_cast<const uint2*>(zp + (size_t)s5 * HID + col);
            uint2 H6 = *reinterpret_cast<const uint2*>(zp + (size_t)s6 * HID + col);
            uint2 H7 = *reinterpret_cast<const uint2*>(zp + (size_t)s7 * HID + col);
            uint2 E0 = *reinterpret_cast<const uint2*>(ep + (size_t)(idx + 0) * HID + col);
            uint2 E1 = *reinterpret_cast<const uint2*>(ep + (size_t)(idx + 1) * HID + col);
            uint2 E2 = *reinterpret_cast<const uint2*>(ep + (size_t)(idx + 2) * HID + col);
            uint2 E3 = *reinterpret_cast<const uint2*>(ep + (size_t)(idx + 3) * HID + col);
            uint2 E4 = *reinterpret_cast<const uint2*>(ep + (size_t)(idx + 4) * HID + col);
            uint2 E5 = *reinterpret_cast<const uint2*>(ep + (size_t)(idx + 5) * HID + col);
            uint2 E6 = *reinterpret_cast<const uint2*>(ep + (size_t)(idx + 6) * HID + col);
            uint2 E7 = *reinterpret_cast<const uint2*>(ep + (size_t)(idx + 7) * HID + col);
            ACCUM2H(H0, E0, H1, E1);
            ACCUM2H(H2_, E2, H3, E3);
            ACCUM2H(H4, E4, H5, E5);
            ACCUM2H(H6, E6, H7, E7);
        }
        if (idx + 4 <= e) {
            int s0 = __ldg(&g_csr_src[idx]);
            int s1 = __ldg(&g_csr_src[idx + 1]);
            int s2 = __ldg(&g_csr_src[idx + 2]);
            int s3 = __ldg(&g_csr_src[idx + 3]);
            uint2 H0 = *reinterpret_cast<const uint2*>(zp + (size_t)s0 * HID + col);
            uint2 H1 = *reinterpret_cast<const uint2*>(zp + (size_t)s1 * HID + col);
            uint2 H2_ = *reinterpret_cast<const uint2*>(zp + (size_t)s2 * HID + col);
            uint2 H3 = *reinterpret_cast<const uint2*>(zp + (size_t)s3 * HID + col);
            uint2 E0 = *reinterpret_cast<const uint2*>(ep + (size_t)(idx + 0) * HID + col);
            uint2 E1 = *reinterpret_cast<const uint2*>(ep + (size_t)(idx + 1) * HID + col);
            uint2 E2 = *reinterpret_cast<const uint2*>(ep + (size_t)(idx + 2) * HID + col);
            uint2 E3 = *reinterpret_cast<const uint2*>(ep + (size_t)(idx + 3) * HID + col);
            ACCUM2H(H0, E0, H1, E1);
            ACCUM2H(H2_, E2, H3, E3);
            idx += 4;
        }
        if (idx + 2 <= e) {
            int s0 = __ldg(&g_csr_src[idx]);
            int s1 = __ldg(&g_csr_src[idx + 1]);
            uint2 H0 = *reinterpret_cast<const uint2*>(zp + (size_t)s0 * HID + col);
            uint2 H1 = *reinterpret_cast<const uint2*>(zp + (size_t)s1 * HID + col);
            uint2 E0 = *reinterpret_cast<const uint2*>(ep + (size_t)(idx + 0) * HID + col);
            uint2 E1 = *reinterpret_cast<const uint2*>(ep + (size_t)(idx + 1) * HID + col);
            ACCUM2H(H0, E0, H1, E1);
            idx += 2;
        }
        if (idx < e) {
            int s0 = __ldg(&g_csr_src[idx]);
            uint2 H0 = *reinterpret_cast<const uint2*>(zp + (size_t)s0 * HID + col);
            uint2 E0 = *reinterpret_cast<const uint2*>(ep + (size_t)idx * HID + col);
            ACCUM1H(H0, E0);
        }
        h16_store4(g_zin16 + (size_t)n * HID + col, acc);
    }
}

// ---------------- MLP via tensor cores (mma.sync m16n8k16) ------------------
#define LDT 136
#define MLP_SMEM_BYTES (4 * HID * LDT * 2 + 2 * HID * 4)
__global__ __launch_bounds__(512, 1)
void mlp_mma_kernel(const __half* __restrict__ W16,
                    const float* __restrict__ B1, const float* __restrict__ B2,
                    float* __restrict__ stats) {
    extern __shared__ __half smh[];
    __half* sW1 = smh;
    __half* sW2 = sW1 + HID * LDT;
    __half* sIn = sW2 + HID * LDT;
    __half* sT  = sIn + HID * LDT;
    float* sB1 = (float*)(sT + HID * LDT);
    float* sB2 = sB1 + HID;

    int tid = threadIdx.x;
    int lane = tid & 31;
    int wid = tid >> 5;
    int wr = wid >> 2;
    int wc = wid & 3;

    for (int i = tid; i < HID * HID; i += 512) {
        int r = i >> 7, c = i & 127;
        sW1[r * LDT + c] = W16[i];
        sW2[r * LDT + c] = W16[HID * HID + i];
    }
    if (tid < HID) { sB1[tid] = B1[tid]; sB2[tid] = B2[tid]; }
    __syncthreads();

    int rpb = (N_NODES + gridDim.x - 1) / gridDim.x;
    int base = blockIdx.x * rpb;
    int rend = min(base + rpb, N_NODES);

    float ls[8], lss[8];
    #pragma unroll
    for (int j = 0; j < 8; j++) { ls[j] = 0.f; lss[j] = 0.f; }

    const int qlane = lane & 3;
    const int rlane = lane >> 2;

    for (int rbase = base; rbase < rend; rbase += HID) {
        for (int i = tid; i < HID * 16; i += 512) {
            int r = i >> 4, q = i & 15;
            int row = rbase + r;
            uint4 v = make_uint4(0u, 0u, 0u, 0u);
            if (row < rend) v = *reinterpret_cast<const uint4*>(g_zin16 + (size_t)row * HID + q * 8);
            *reinterpret_cast<uint4*>(&sIn[r * LDT + q * 8]) = v;
        }
        __syncthreads();

        float acc[2][4][4];
        #pragma unroll
        for (int mb = 0; mb < 2; mb++)
            #pragma unroll
            for (int nb = 0; nb < 4; nb++)
                #pragma unroll
                for (int j = 0; j < 4; j++) acc[mb][nb][j] = 0.f;

        #pragma unroll
        for (int ks = 0; ks < 8; ks++) {
            int k0 = ks * 16;
            unsigned a[2][4];
            #pragma unroll
            for (int mb = 0; mb < 2; mb++) {
                int row = wr * 32 + mb * 16 + (lane & 15);
                unsigned addr = smem_u32(&sIn[row * LDT + k0 + ((lane >> 4) << 3)]);
                ldsm_x4(addr, a[mb][0], a[mb][1], a[mb][2], a[mb][3]);
            }
            unsigned b[4][2];
            #pragma unroll
            for (int np = 0; np < 2; np++) {
                int krow = k0 + (lane & 15);
                int n0 = wc * 32 + np * 16 + ((lane >> 4) << 3);
                unsigned addr = smem_u32(&sW1[krow * LDT + n0]);
                unsigned r0, r1, r2, r3;
                ldsm_x4_t(addr, r0, r1, r2, r3);
                b[2 * np][0] = r0; b[2 * np][1] = r1;
                b[2 * np + 1][0] = r2; b[2 * np + 1][1] = r3;
            }
            #pragma unroll
            for (int mb = 0; mb < 2; mb++)
                #pragma unroll
                for (int nb = 0; nb < 4; nb++)
                    mma16816(acc[mb][nb][0], acc[mb][nb][1], acc[mb][nb][2], acc[mb][nb][3],
                             a[mb][0], a[mb][1], a[mb][2], a[mb][3], b[nb][0], b[nb][1]);
        }
        __syncthreads();
        #pragma unroll
        for (int mb = 0; mb < 2; mb++) {
            #pragma unroll
            for (int nb = 0; nb < 4; nb++) {
                int col = wc * 32 + nb * 8 + 2 * qlane;
                float bx = sB1[col], by = sB1[col + 1];
                int rlo = wr * 32 + mb * 16 + rlane;
                *reinterpret_cast<__half2*>(&sT[rlo * LDT + col]) =
                    __floats2half2_rn(fmaxf(acc[mb][nb][0] + bx, 0.f),
                                      fmaxf(acc[mb][nb][1] + by, 0.f));
                *reinterpret_cast<__half2*>(&sT[(rlo + 8) * LDT + col]) =
                    __floats2half2_rn(fmaxf(acc[mb][nb][2] + bx, 0.f),
                                      fmaxf(acc[mb][nb][3] + by, 0.f));
            }
        }
        __syncthreads();

        #pragma unroll
        for (int mb = 0; mb < 2; mb++)
            #pragma unroll
            for (int nb = 0; nb < 4; nb++)
                #pragma unroll
                for (int j = 0; j < 4; j++) acc[mb][nb][j] = 0.f;

        #pragma unroll
        for (int ks = 0; ks < 8; ks++) {
            int k0 = ks * 16;
            unsigned a[2][4];
            #pragma unroll
            for (int mb = 0; mb < 2; mb++) {
                int row = wr * 32 + mb * 16 + (lane & 15);
                unsigned addr = smem_u32(&sT[row * LDT + k0 + ((lane >> 4) << 3)]);
                ldsm_x4(addr, a[mb][0], a[mb][1], a[mb][2], a[mb][3]);
            }
            unsigned b[4][2];
            #pragma unroll
            for (int np = 0; np < 2; np++) {
                int krow = k0 + (lane & 15);
                int n0 = wc * 32 + np * 16 + ((lane >> 4) << 3);
                unsigned addr = smem_u32(&sW2[krow * LDT + n0]);
                unsigned r0, r1, r2, r3;
                ldsm_x4_t(addr, r0, r1, r2, r3);
                b[2 * np][0] = r0; b[2 * np][1] = r1;
                b[2 * np + 1][0] = r2; b[2 * np + 1][1] = r3;
            }
            #pragma unroll
            for (int mb = 0; mb < 2; mb++)
                #pragma unroll
                for (int nb = 0; nb < 4; nb++)
                    mma16816(acc[mb][nb][0], acc[mb][nb][1], acc[mb][nb][2], acc[mb][nb][3],
                             a[mb][0], a[mb][1], a[mb][2], a[mb][3], b[nb][0], b[nb][1]);
        }
        #pragma unroll
        for (int mb = 0; mb < 2; mb++) {
            #pragma unroll
            for (int nb = 0; nb < 4; nb++) {
                int col = wc * 32 + nb * 8 + 2 * qlane;
                float bx = sB2[col], by = sB2[col + 1];
                int rlo = rbase + wr * 32 + mb * 16 + rlane;
                float z0 = acc[mb][nb][0] + bx, z1 = acc[mb][nb][1] + by;
                float z2 = acc[mb][nb][2] + bx, z3 = acc[mb][nb][3] + by;
                if (rlo < rend) {
                    *reinterpret_cast<__half2*>(&g_z16[(size_t)rlo * HID + col]) =
                        __floats2half2_rn(z0, z1);
                    ls[2 * nb] += z0; lss[2 * nb] += z0 * z0;
                    ls[2 * nb + 1] += z1; lss[2 * nb + 1] += z1 * z1;
                }
                if (rlo + 8 < rend) {
                    *reinterpret_cast<__half2*>(&g_z16[(size_t)(rlo + 8) * HID + col]) =
                        __floats2half2_rn(z2, z3);
                    ls[2 * nb] += z2; lss[2 * nb] += z2 * z2;
                    ls[2 * nb + 1] += z3; lss[2 * nb + 1] += z3 * z3;
                }
            }
        }
        __syncthreads();
    }

    #pragma unroll
    for (int j = 0; j < 8; j++) {
        #pragma unroll
        for (int o = 4; o < 32; o <<= 1) {
            ls[j]  += __shfl_xor_sync(0xffffffffu, ls[j], o);
            lss[j] += __shfl_xor_sync(0xffffffffu, lss[j], o);
        }
    }
    if (lane < 4) {
        #pragma unroll
        for (int nb = 0; nb < 4; nb++) {
            #pragma unroll
            for (int j = 0; j < 2; j++) {
                int col = wc * 32 + nb * 8 + 2 * lane + j;
                atomicAdd(&stats[col], ls[2 * nb + j]);
                atomicAdd(&stats[HID + col], lss[2 * nb + j]);
            }
        }
    }
}

// ---------------- last layer: BN + relu + pool (reads z16) ------------------
__global__ void bn_pool_kernel(const float* __restrict__ gamma,
                               const float* __restrict__ beta,
                               const float* __restrict__ stats,
                               const int* __restrict__ batch) {
    int i = blockIdx.x * blockDim.x + threadIdx.x;
    const int n4 = N_NODES * HID / 4;
    if (i >= n4) return;
    int n = i >> 5;
    int c0 = (i & 31) * 4;
    float4 z = h16_load4(g_z16 + (size_t)i * 4);
    float za[4] = {z.x, z.y, z.z, z.w};
    float out[4];
    const float invN = 1.0f / (float)N_NODES;
    #pragma unroll
    for (int j = 0; j < 4; j++) {
        int c = c0 + j;
        float mean = stats[c] * invN;
        float var = stats[HID + c] * invN - mean * mean;
        float rstd = rsqrtf(var + BN_EPS);
        float o = gamma[c] * (za[j] - mean) * rstd + beta[c];
        out[j] = fmaxf(o, 0.f);
    }
    int gi = __ldg(&batch[n]);
    red_add_v4(g_pool + (size_t)gi * HID + c0,
               make_float4(out[0], out[1], out[2], out[3]));
}

// ---------------- head: out = relu(g@W1+b1)@W2+b2 ---------------------------
__global__ void head_kernel(const float* __restrict__ w1, const float* __restrict__ b1,
                            const float* __restrict__ w2, const float* __restrict__ b2,
                            float* __restrict__ out) {
    __shared__ float srow[HID];
    __shared__ float st[HID];
    int gi = blockIdx.x;
    int c = threadIdx.x;
    srow[c] = g_pool[(size_t)gi * HID + c];
    __syncthreads();
    float acc = b1[c];
    for (int k = 0; k < HID; k++) acc += srow[k] * w1[k * HID + c];
    st[c] = fmaxf(acc, 0.f);
    __syncthreads();
    if (c < 2) {
        float o = b2[c];
        for (int k = 0; k < HID; k++) o += st[k] * w2[k * 2 + c];
        out[gi * 2 + c] = o;
    }
}

// ---------------- launch -----------------------------------------------------
extern "C" void kernel_launch(void* const* d_in, const int* in_sizes, int n_in,
                              void* d_out, int out_size) {
    const float* x        = (const float*)d_in[0];
    const int*   eidx     = (const int*)d_in[1];
    const float* eattr    = (const float*)d_in[2];
    const int*   batch    = (const int*)d_in[3];
    const float* node_w   = (const float*)d_in[4];
    const float* node_b   = (const float*)d_in[5];
    const float* edge_w   = (const float*)d_in[6];
    const float* edge_b   = (const float*)d_in[7];
    const float* mlp_w1   = (const float*)d_in[8];
    const float* mlp_b1   = (const float*)d_in[9];
    const float* mlp_w2   = (const float*)d_in[10];
    const float* mlp_b2   = (const float*)d_in[11];
    const float* bn_gamma = (const float*)d_in[12];
    const float* bn_beta  = (const float*)d_in[13];
    const float* head_w1  = (const float*)d_in[14];
    const float* head_b1  = (const float*)d_in[15];
    const float* head_w2  = (const float*)d_in[16];
    const float* head_b2  = (const float*)d_in[17];
    float* out = (float*)d_out;

    cudaFuncSetAttribute(mlp_mma_kernel, cudaFuncAttributeMaxDynamicSharedMemorySize,
                         MLP_SMEM_BYTES);

    float* d_stats;
    cudaGetSymbolAddress((void**)&d_stats, g_stats);
    __half* d_w16;
    cudaGetSymbolAddress((void**)&d_w16, g_w16);

    convert_w_kernel<<<(2 * NLAYERS * HID * HID + 255) / 256, 256>>>(mlp_w1, mlp_w2);
    csr_count_kernel<<<(N_EDGES + 255) / 256, 256>>>(eidx);
    chunk_sum_kernel<<<NCHUNK / 128, 128>>>();
    chunk_scan_kernel<<<1, NCHUNK>>>();
    chunk_offs_kernel<<<NCHUNK / 128, 128>>>();
    edge_enc_mma_kernel<<<592, 512>>>(eattr, eidx, edge_w, edge_b);
    encoder_kernel<<<512, 256>>>(x, node_w, node_b);

    const int grid_elem = (N_NODES * HID / 4 + 255) / 256;
    for (int l = 0; l < NLAYERS; l++) {
        agg_kernel<<<4096, 256>>>();
        mlp_mma_kernel<<<148, 512, MLP_SMEM_BYTES>>>(
            d_w16 + (size_t)l * 2 * HID * HID,
            mlp_b1 + (size_t)l * HID,
            mlp_b2 + (size_t)l * HID,
            d_stats + (size_t)l * 2 * HID);
        if (l < NLAYERS - 1) {
            bn_apply_kernel<<<grid_elem, 256>>>(bn_gamma + (size_t)l * HID,
                                                bn_beta + (size_t)l * HID,
                                                d_stats + (size_t)l * 2 * HID);
        }
    }

    bn_pool_kernel<<<grid_elem, 256>>>(
        bn_gamma + (size_t)(NLAYERS - 1) * HID,
        bn_beta + (size_t)(NLAYERS - 1) * HID,
        d_stats + (size_t)(NLAYERS - 1) * 2 * HID, batch);
    head_kernel<<<NGRAPHS, HID>>>(head_w1, head_b1, head_w2, head_b2, out);
}

// round 17
// speedup vs baseline: 1.4093x; 1.0358x over previous
#include <cuda_runtime.h>
#include <cuda_fp16.h>

#define N_NODES 50000
#define N_EDGES 600000
#define HID 128
#define NODE_DIM 64
#define EDGE_DIM 16
#define NLAYERS 3
#define NGRAPHS 256
#define BN_EPS 1e-5f

typedef unsigned long long u64;

// ---------------- scratch (device globals; no allocations allowed) ----------
__device__ __half g_z16[N_NODES * HID];    // node features (post bn_apply) / pre-BN z
__device__ __half g_zin16[N_NODES * HID];  // h + agg (MLP input), fp16
__device__ __half g_ea_h[N_EDGES * HID];   // encoded edge features, fp16, CSR order
__device__ __half g_w16[NLAYERS * 2 * HID * HID];  // fp16 MLP weights
__device__ float g_stats[NLAYERS * 2 * HID]; // per-layer column sums / sumsq
__device__ float g_pool[NGRAPHS * HID];    // pooled graph features
// CSR by destination
__device__ int g_cnt[N_NODES];
__device__ int g_off[N_NODES + 1];
__device__ int g_cur[N_NODES];
__device__ int g_csr_src[N_EDGES];
// parallel scan scratch
#define NCHUNK 1024
#define CHSZ ((N_NODES + NCHUNK - 1) / NCHUNK)
__device__ int g_chunk[NCHUNK];
__device__ int g_chunk_base[NCHUNK];

// ---------------- helpers ----------------------------------------------------
__device__ __forceinline__ void red_add_v4(float* p, float4 v) {
    asm volatile("red.global.add.v4.f32 [%0], {%1,%2,%3,%4};"
                 :: "l"(p), "f"(v.x), "f"(v.y), "f"(v.z), "f"(v.w) : "memory");
}

__device__ __forceinline__ float4 h16_load4(const __half* p) {
    uint2 u = *reinterpret_cast<const uint2*>(p);
    __half2 a = *reinterpret_cast<__half2*>(&u.x);
    __half2 b = *reinterpret_cast<__half2*>(&u.y);
    float2 fa = __half22float2(a);
    float2 fb = __half22float2(b);
    return make_float4(fa.x, fa.y, fb.x, fb.y);
}
__device__ __forceinline__ float4 u2_to_f4(uint2 u) {
    __half2 a = *reinterpret_cast<__half2*>(&u.x);
    __half2 b = *reinterpret_cast<__half2*>(&u.y);
    float2 fa = __half22float2(a);
    float2 fb = __half22float2(b);
    return make_float4(fa.x, fa.y, fb.x, fb.y);
}
__device__ __forceinline__ void h16_store4(__half* p, float4 v) {
    union { __half2 h[2]; uint2 u; } cv;
    cv.h[0] = __floats2half2_rn(v.x, v.y);
    cv.h[1] = __floats2half2_rn(v.z, v.w);
    *reinterpret_cast<uint2*>(p) = cv.u;
}

__device__ __forceinline__ unsigned smem_u32(const void* p) {
    return (unsigned)__cvta_generic_to_shared(p);
}
__device__ __forceinline__ void ldsm_x4(unsigned addr, unsigned& r0, unsigned& r1,
                                        unsigned& r2, unsigned& r3) {
    asm volatile("ldmatrix.sync.aligned.m8n8.x4.shared.b16 {%0,%1,%2,%3},[%4];"
                 : "=r"(r0), "=r"(r1), "=r"(r2), "=r"(r3) : "r"(addr));
}
__device__ __forceinline__ void ldsm_x4_t(unsigned addr, unsigned& r0, unsigned& r1,
                                          unsigned& r2, unsigned& r3) {
    asm volatile("ldmatrix.sync.aligned.m8n8.x4.trans.shared.b16 {%0,%1,%2,%3},[%4];"
                 : "=r"(r0), "=r"(r1), "=r"(r2), "=r"(r3) : "r"(addr));
}
__device__ __forceinline__ void mma16816(float& c0, float& c1, float& c2, float& c3,
                                         unsigned a0, unsigned a1, unsigned a2, unsigned a3,
                                         unsigned b0, unsigned b1) {
    asm volatile("mma.sync.aligned.m16n8k16.row.col.f32.f16.f16.f32 "
                 "{%0,%1,%2,%3},{%4,%5,%6,%7},{%8,%9},{%0,%1,%2,%3};"
                 : "+f"(c0), "+f"(c1), "+f"(c2), "+f"(c3)
                 : "r"(a0), "r"(a1), "r"(a2), "r"(a3), "r"(b0), "r"(b1));
}

// ---------------- zero cnt (stream 1 head) ----------------------------------
__global__ void zero_cnt_kernel() {
    int i = blockIdx.x * blockDim.x + threadIdx.x;
    if (i < N_NODES) g_cnt[i] = 0;
}

// ---------------- weight conversion + pool/stats zeroing (stream 3) ---------
__global__ void convert_w_kernel(const float* __restrict__ w1,
                                 const float* __restrict__ w2) {
    int gt = blockIdx.x * blockDim.x + threadIdx.x;
    int gsz = gridDim.x * blockDim.x;
    for (int i = gt; i < NGRAPHS * HID; i += gsz) g_pool[i] = 0.f;
    for (int i = gt; i < NLAYERS * 2 * HID; i += gsz) g_stats[i] = 0.f;

    int i = gt;
    const int per = NLAYERS * HID * HID;
    if (i < per) {
        int l = i / (HID * HID);
        int j = i % (HID * HID);
        g_w16[(size_t)l * 2 * HID * HID + j] = __float2half(w1[i]);
    } else if (i < 2 * per) {
        int k = i - per;
        int l = k / (HID * HID);
        int j = k % (HID * HID);
        g_w16[(size_t)l * 2 * HID * HID + HID * HID + j] = __float2half(w2[k]);
    }
}

// ---------------- CSR build --------------------------------------------------
__global__ void csr_count_kernel(const int* __restrict__ eidx) {
    int e = blockIdx.x * blockDim.x + threadIdx.x;
    if (e < N_EDGES) atomicAdd(&g_cnt[eidx[N_EDGES + e]], 1);
}

__global__ void chunk_sum_kernel() {
    int t = blockIdx.x * blockDim.x + threadIdx.x;
    if (t >= NCHUNK) return;
    int beg = t * CHSZ;
    int end = min(beg + CHSZ, N_NODES);
    int s = 0;
    for (int i = beg; i < end; i++) s += g_cnt[i];
    g_chunk[t] = s;
}

__global__ void chunk_scan_kernel() {
    __shared__ int ssum[NCHUNK];
    int t = threadIdx.x;
    ssum[t] = g_chunk[t];
    __syncthreads();
    for (int off = 1; off < NCHUNK; off <<= 1) {
        int v = (t >= off) ? ssum[t - off] : 0;
        __syncthreads();
        ssum[t] += v;
        __syncthreads();
    }
    g_chunk_base[t] = (t == 0) ? 0 : ssum[t - 1];
    if (t == NCHUNK - 1) g_off[N_NODES] = ssum[t];
}

__global__ void chunk_offs_kernel() {
    int t = blockIdx.x * blockDim.x + threadIdx.x;
    if (t >= NCHUNK) return;
    int beg = t * CHSZ;
    int end = min(beg + CHSZ, N_NODES);
    int run = g_chunk_base[t];
    for (int i = beg; i < end; i++) {
        g_off[i] = run;
        g_cur[i] = run;
        run += g_cnt[i];
    }
}

// --- edge encoder via tensor cores + fused csr_fill --------------------------
#define LDTE 136   // sW row stride (halves)
#define LDA 24     // sA row stride (halves)
__global__ __launch_bounds__(512)
void edge_enc_mma_kernel(const float* __restrict__ eattr,
                         const int* __restrict__ eidx,
                         const float* __restrict__ W,
                         const float* __restrict__ b) {
    __shared__ __half sW[EDGE_DIM * LDTE];
    __shared__ __half sA[128 * LDA];
    __shared__ float sbb[HID];
    __shared__ int sslot[128];

    int tid = threadIdx.x;
    int lane = tid & 31;
    int wid = tid >> 5;
    int wr = wid >> 2;
    int wc = wid & 3;

    for (int i = tid; i < EDGE_DIM * HID; i += 512) {
        int k = i >> 7, n = i & 127;
        sW[k * LDTE + n] = __float2half(W[i]);
    }
    if (tid < HID) sbb[tid] = b[tid];
    __syncthreads();

    const int qlane = lane & 3;
    const int rlane = lane >> 2;
    const int ntiles = (N_EDGES + 127) / 128;

    for (int tile = blockIdx.x; tile < ntiles; tile += gridDim.x) {
        int e0 = tile * 128;
        for (int i = tid; i < 128 * EDGE_DIM; i += 512) {
            int r = i >> 4, c = i & 15;
            int e = e0 + r;
            float v = (e < N_EDGES) ? eattr[(size_t)e * EDGE_DIM + c] : 0.f;
            sA[r * LDA + c] = __float2half(v);
        }
        if (tid < 128) {
            int e = e0 + tid;
            int slot = -1;
            if (e < N_EDGES) {
                int src = eidx[e];
                int dst = eidx[N_EDGES + e];
                slot = atomicAdd(&g_cur[dst], 1);
                g_csr_src[slot] = src;
            }
            sslot[tid] = slot;
        }
        __syncthreads();

        float acc[2][4][4];
        #pragma unroll
        for (int mb = 0; mb < 2; mb++)
            #pragma unroll
            for (int nb = 0; nb < 4; nb++)
                #pragma unroll
                for (int j = 0; j < 4; j++) acc[mb][nb][j] = 0.f;

        unsigned a[2][4];
        #pragma unroll
        for (int mb = 0; mb < 2; mb++) {
            int row = wr * 32 + mb * 16 + (lane & 15);
            unsigned addr = smem_u32(&sA[row * LDA + ((lane >> 4) << 3)]);
            ldsm_x4(addr, a[mb][0], a[mb][1], a[mb][2], a[mb][3]);
        }
        unsigned bf[4][2];
        #pragma unroll
        for (int np = 0; np < 2; np++) {
            int krow = lane & 15;
            int n0 = wc * 32 + np * 16 + ((lane >> 4) << 3);
            unsigned addr = smem_u32(&sW[krow * LDTE + n0]);
            unsigned r0, r1, r2, r3;
            ldsm_x4_t(addr, r0, r1, r2, r3);
            bf[2 * np][0] = r0; bf[2 * np][1] = r1;
            bf[2 * np + 1][0] = r2; bf[2 * np + 1][1] = r3;
        }
        #pragma unroll
        for (int mb = 0; mb < 2; mb++)
            #pragma unroll
            for (int nb = 0; nb < 4; nb++)
                mma16816(acc[mb][nb][0], acc[mb][nb][1], acc[mb][nb][2], acc[mb][nb][3],
                         a[mb][0], a[mb][1], a[mb][2], a[mb][3], bf[nb][0], bf[nb][1]);

        #pragma unroll
        for (int mb = 0; mb < 2; mb++) {
            #pragma unroll
            for (int nb = 0; nb < 4; nb++) {
                int col = wc * 32 + nb * 8 + 2 * qlane;
                float bx = sbb[col], by = sbb[col + 1];
                int r0i = wr * 32 + mb * 16 + rlane;
                int s0 = sslot[r0i];
                if (s0 >= 0)
                    *reinterpret_cast<__half2*>(&g_ea_h[(size_t)s0 * HID + col]) =
                        __floats2half2_rn(acc[mb][nb][0] + bx, acc[mb][nb][1] + by);
                int s1 = sslot[r0i + 8];
                if (s1 >= 0)
                    *reinterpret_cast<__half2*>(&g_ea_h[(size_t)s1 * HID + col]) =
                        __floats2half2_rn(acc[mb][nb][2] + bx, acc[mb][nb][3] + by);
            }
        }
        __syncthreads();
    }
}

// ---------------- node encoder: z16 = x @ node_w + node_b -------------------
__global__ void encoder_kernel(const float* __restrict__ x,
                               const float* __restrict__ W,
                               const float* __restrict__ b) {
    __shared__ float sW[NODE_DIM * HID];
    for (int i = threadIdx.x; i < NODE_DIM * HID; i += blockDim.x) sW[i] = W[i];
    __syncthreads();
    int lane = threadIdx.x & 31;
    int warp = (blockIdx.x * blockDim.x + threadIdx.x) >> 5;
    int nw = (gridDim.x * blockDim.x) >> 5;
    float4 bb = reinterpret_cast<const float4*>(b)[lane];
    for (int n = warp; n < N_NODES; n += nw) {
        const float4* xr = reinterpret_cast<const float4*>(x + (size_t)n * NODE_DIM);
        float4 acc = bb;
        #pragma unroll
        for (int kk = 0; kk < NODE_DIM / 4; kk++) {
            float4 xv = xr[kk];
            float xa[4] = {xv.x, xv.y, xv.z, xv.w};
            #pragma unroll
            for (int j = 0; j < 4; j++) {
                float4 w = *reinterpret_cast<const float4*>(&sW[(4 * kk + j) * HID + 4 * lane]);
                acc.x += xa[j] * w.x;
                acc.y += xa[j] * w.y;
                acc.z += xa[j] * w.z;
                acc.w += xa[j] * w.w;
            }
        }
        h16_store4(g_z16 + (size_t)n * HID + 4 * lane, acc);
    }
}

// ---- bn_apply: z16 <- relu(bn(z16)) in place (layers 0..NLAYERS-2) ---------
__global__ void bn_apply_kernel(const float* __restrict__ gamma,
                                const float* __restrict__ beta,
                                const float* __restrict__ stats) {
    int i = blockIdx.x * blockDim.x + threadIdx.x;
    const int n4 = N_NODES * HID / 4;
    if (i >= n4) return;
    int c0 = (i & 31) * 4;
    float4 z = h16_load4(g_z16 + (size_t)i * 4);
    float za[4] = {z.x, z.y, z.z, z.w};
    float out[4];
    const float invN = 1.0f / (float)N_NODES;
    #pragma unroll
    for (int j = 0; j < 4; j++) {
        int c = c0 + j;
        float mean = stats[c] * invN;
        float var = stats[HID + c] * invN - mean * mean;
        float rstd = rsqrtf(var + BN_EPS);
        float o = gamma[c] * (za[j] - mean) * rstd + beta[c];
        out[j] = fmaxf(o, 0.f);
    }
    h16_store4(g_z16 + (size_t)i * 4, make_float4(out[0], out[1], out[2], out[3]));
}

// ---- aggregation (BN-free, half2 message math) ------------------------------
#define H2(u) (*reinterpret_cast<const __half2*>(&(u)))

#define ACCUM2H(Ha, Ea, Hb, Eb) do { \
    __half2 mlo = __hadd2(__hmax2(__hadd2(H2(Ha.x), H2(Ea.x)), z2), \
                          __hmax2(__hadd2(H2(Hb.x), H2(Eb.x)), z2)); \
    __half2 mhi = __hadd2(__hmax2(__hadd2(H2(Ha.y), H2(Ea.y)), z2), \
                          __hmax2(__hadd2(H2(Hb.y), H2(Eb.y)), z2)); \
    float2 f0 = __half22float2(mlo); \
    float2 f1 = __half22float2(mhi); \
    acc.x += f0.x; acc.y += f0.y; acc.z += f1.x; acc.w += f1.y; \
} while (0)

#define ACCUM1H(H, E) do { \
    __half2 mlo = __hmax2(__hadd2(H2(H.x), H2(E.x)), z2); \
    __half2 mhi = __hmax2(__hadd2(H2(H.y), H2(E.y)), z2); \
    float2 f0 = __half22float2(mlo); \
    float2 f1 = __half22float2(mhi); \
    acc.x += f0.x; acc.y += f0.y; acc.z += f1.x; acc.w += f1.y; \
} while (0)

__global__ __launch_bounds__(256, 4)
void agg_kernel() {
    int lane = threadIdx.x & 31;
    int warp = (blockIdx.x * blockDim.x + threadIdx.x) >> 5;
    int nw = (gridDim.x * blockDim.x) >> 5;
    const __half* zp = g_z16;
    const __half* ep = g_ea_h;
    const int col = 4 * lane;
    const __half2 z2 = __float2half2_rn(0.f);

    for (int n = warp; n < N_NODES; n += nw) {
        float4 acc = u2_to_f4(*reinterpret_cast<const uint2*>(zp + (size_t)n * HID + col));
        int s = __ldg(&g_off[n]);
        int e = __ldg(&g_off[n + 1]);
        int idx = s;
        for (; idx + 8 <= e; idx += 8) {
            int s0 = __ldg(&g_csr_src[idx]);
            int s1 = __ldg(&g_csr_src[idx + 1]);
            int s2 = __ldg(&g_csr_src[idx + 2]);
            int s3 = __ldg(&g_csr_src[idx + 3]);
            int s4 = __ldg(&g_csr_src[idx + 4]);
            int s5 = __ldg(&g_csr_src[idx + 5]);
            int s6 = __ldg(&g_csr_src[idx + 6]);
            int s7 = __ldg(&g_csr_src[idx + 7]);
            uint2 H0 = *reinterpret_cast<const uint2*>(zp + (size_t)s0 * HID + col);
            uint2 H1 = *reinterpret_cast<const uint2*>(zp + (size_t)s1 * HID + col);
            uint2 H2_ = *reinterpret_cast<const uint2*>(zp + (size_t)s2 * HID + col);
            uint2 H3 = *reinterpret_cast<const uint2*>(zp + (size_t)s3 * HID + col);
            uint2 H4 = *reinterpret_cast<const uint2*>(zp + (size_t)s4 * HID + col);
            uint2 H5 = *reinterpret_cast<const uint2*>(zp + (size_t)s5 * HID + col);
            uint2 H6 = *reinterpret_cast<const uint2*>(zp + (size_t)s6 * HID + col);
            uint2 H7 = *reinterpret_cast<const uint2*>(zp + (size_t)s7 * HID + col);
            uint2 E0 = *reinterpret_cast<const uint2*>(ep + (size_t)(idx + 0) * HID + col);
            uint2 E1 = *reinterpret_cast<const uint2*>(ep + (size_t)(idx + 1) * HID + col);
            uint2 E2 = *reinterpret_cast<const uint2*>(ep + (size_t)(idx + 2) * HID + col);
            uint2 E3 = *reinterpret_cast<const uint2*>(ep + (size_t)(idx + 3) * HID + col);
            uint2 E4 = *reinterpret_cast<const uint2*>(ep + (size_t)(idx + 4) * HID + col);
            uint2 E5 = *reinterpret_cast<const uint2*>(ep + (size_t)(idx + 5) * HID + col);
            uint2 E6 = *reinterpret_cast<const uint2*>(ep + (size_t)(idx + 6) * HID + col);
            uint2 E7 = *reinterpret_cast<const uint2*>(ep + (size_t)(idx + 7) * HID + col);
            ACCUM2H(H0, E0, H1, E1);
            ACCUM2H(H2_, E2, H3, E3);
            ACCUM2H(H4, E4, H5, E5);
            ACCUM2H(H6, E6, H7, E7);
        }
        if (idx + 4 <= e) {
            int s0 = __ldg(&g_csr_src[idx]);
            int s1 = __ldg(&g_csr_src[idx + 1]);
            int s2 = __ldg(&g_csr_src[idx + 2]);
            int s3 = __ldg(&g_csr_src[idx + 3]);
            uint2 H0 = *reinterpret_cast<const uint2*>(zp + (size_t)s0 * HID + col);
            uint2 H1 = *reinterpret_cast<const uint2*>(zp + (size_t)s1 * HID + col);
            uint2 H2_ = *reinterpret_cast<const uint2*>(zp + (size_t)s2 * HID + col);
            uint2 H3 = *reinterpret_cast<const uint2*>(zp + (size_t)s3 * HID + col);
            uint2 E0 = *reinterpret_cast<const uint2*>(ep + (size_t)(idx + 0) * HID + col);
            uint2 E1 = *reinterpret_cast<const uint2*>(ep + (size_t)(idx + 1) * HID + col);
            uint2 E2 = *reinterpret_cast<const uint2*>(ep + (size_t)(idx + 2) * HID + col);
            uint2 E3 = *reinterpret_cast<const uint2*>(ep + (size_t)(idx + 3) * HID + col);
            ACCUM2H(H0, E0, H1, E1);
            ACCUM2H(H2_, E2, H3, E3);
            idx += 4;
        }
        if (idx + 2 <= e) {
            int s0 = __ldg(&g_csr_src[idx]);
            int s1 = __ldg(&g_csr_src[idx + 1]);
            uint2 H0 = *reinterpret_cast<const uint2*>(zp + (size_t)s0 * HID + col);
            uint2 H1 = *reinterpret_cast<const uint2*>(zp + (size_t)s1 * HID + col);
            uint2 E0 = *reinterpret_cast<const uint2*>(ep + (size_t)(idx + 0) * HID + col);
            uint2 E1 = *reinterpret_cast<const uint2*>(ep + (size_t)(idx + 1) * HID + col);
            ACCUM2H(H0, E0, H1, E1);
            idx += 2;
        }
        if (idx < e) {
            int s0 = __ldg(&g_csr_src[idx]);
            uint2 H0 = *reinterpret_cast<const uint2*>(zp + (size_t)s0 * HID + col);
            uint2 E0 = *reinterpret_cast<const uint2*>(ep + (size_t)idx * HID + col);
            ACCUM1H(H0, E0);
        }
        h16_store4(g_zin16 + (size_t)n * HID + col, acc);
    }
}

// ---------------- MLP via tensor cores (mma.sync m16n8k16) ------------------
#define LDT 136
#define MLP_SMEM_BYTES (4 * HID * LDT * 2 + 2 * HID * 4)
__global__ __launch_bounds__(512, 1)
void mlp_mma_kernel(const __half* __restrict__ W16,
                    const float* __restrict__ B1, const float* __restrict__ B2,
                    float* __restrict__ stats) {
    extern __shared__ __half smh[];
    __half* sW1 = smh;
    __half* sW2 = sW1 + HID * LDT;
    __half* sIn = sW2 + HID * LDT;
    __half* sT  = sIn + HID * LDT;
    float* sB1 = (float*)(sT + HID * LDT);
    float* sB2 = sB1 + HID;

    int tid = threadIdx.x;
    int lane = tid & 31;
    int wid = tid >> 5;
    int wr = wid >> 2;
    int wc = wid & 3;

    for (int i = tid; i < HID * HID; i += 512) {
        int r = i >> 7, c = i & 127;
        sW1[r * LDT + c] = W16[i];
        sW2[r * LDT + c] = W16[HID * HID + i];
    }
    if (tid < HID) { sB1[tid] = B1[tid]; sB2[tid] = B2[tid]; }
    __syncthreads();

    int rpb = (N_NODES + gridDim.x - 1) / gridDim.x;
    int base = blockIdx.x * rpb;
    int rend = min(base + rpb, N_NODES);

    float ls[8], lss[8];
    #pragma unroll
    for (int j = 0; j < 8; j++) { ls[j] = 0.f; lss[j] = 0.f; }

    const int qlane = lane & 3;
    const int rlane = lane >> 2;

    for (int rbase = base; rbase < rend; rbase += HID) {
        for (int i = tid; i < HID * 16; i += 512) {
            int r = i >> 4, q = i & 15;
            int row = rbase + r;
            uint4 v = make_uint4(0u, 0u, 0u, 0u);
            if (row < rend) v = *reinterpret_cast<const uint4*>(g_zin16 + (size_t)row * HID + q * 8);
            *reinterpret_cast<uint4*>(&sIn[r * LDT + q * 8]) = v;
        }
        __syncthreads();

        float acc[2][4][4];
        #pragma unroll
        for (int mb = 0; mb < 2; mb++)
            #pragma unroll
            for (int nb = 0; nb < 4; nb++)
                #pragma unroll
                for (int j = 0; j < 4; j++) acc[mb][nb][j] = 0.f;

        #pragma unroll
        for (int ks = 0; ks < 8; ks++) {
            int k0 = ks * 16;
            unsigned a[2][4];
            #pragma unroll
            for (int mb = 0; mb < 2; mb++) {
                int row = wr * 32 + mb * 16 + (lane & 15);
                unsigned addr = smem_u32(&sIn[row * LDT + k0 + ((lane >> 4) << 3)]);
                ldsm_x4(addr, a[mb][0], a[mb][1], a[mb][2], a[mb][3]);
            }
            unsigned b[4][2];
            #pragma unroll
            for (int np = 0; np < 2; np++) {
                int krow = k0 + (lane & 15);
                int n0 = wc * 32 + np * 16 + ((lane >> 4) << 3);
                unsigned addr = smem_u32(&sW1[krow * LDT + n0]);
                unsigned r0, r1, r2, r3;
                ldsm_x4_t(addr, r0, r1, r2, r3);
                b[2 * np][0] = r0; b[2 * np][1] = r1;
                b[2 * np + 1][0] = r2; b[2 * np + 1][1] = r3;
            }
            #pragma unroll
            for (int mb = 0; mb < 2; mb++)
                #pragma unroll
                for (int nb = 0; nb < 4; nb++)
                    mma16816(acc[mb][nb][0], acc[mb][nb][1], acc[mb][nb][2], acc[mb][nb][3],
                             a[mb][0], a[mb][1], a[mb][2], a[mb][3], b[nb][0], b[nb][1]);
        }
        __syncthreads();
        #pragma unroll
        for (int mb = 0; mb < 2; mb++) {
            #pragma unroll
            for (int nb = 0; nb < 4; nb++) {
                int col = wc * 32 + nb * 8 + 2 * qlane;
                float bx = sB1[col], by = sB1[col + 1];
                int rlo = wr * 32 + mb * 16 + rlane;
                *reinterpret_cast<__half2*>(&sT[rlo * LDT + col]) =
                    __floats2half2_rn(fmaxf(acc[mb][nb][0] + bx, 0.f),
                                      fmaxf(acc[mb][nb][1] + by, 0.f));
                *reinterpret_cast<__half2*>(&sT[(rlo + 8) * LDT + col]) =
                    __floats2half2_rn(fmaxf(acc[mb][nb][2] + bx, 0.f),
                                      fmaxf(acc[mb][nb][3] + by, 0.f));
            }
        }
        __syncthreads();

        #pragma unroll
        for (int mb = 0; mb < 2; mb++)
            #pragma unroll
            for (int nb = 0; nb < 4; nb++)
                #pragma unroll
                for (int j = 0; j < 4; j++) acc[mb][nb][j] = 0.f;

        #pragma unroll
        for (int ks = 0; ks < 8; ks++) {
            int k0 = ks * 16;
            unsigned a[2][4];
            #pragma unroll
            for (int mb = 0; mb < 2; mb++) {
                int row = wr * 32 + mb * 16 + (lane & 15);
                unsigned addr = smem_u32(&sT[row * LDT + k0 + ((lane >> 4) << 3)]);
                ldsm_x4(addr, a[mb][0], a[mb][1], a[mb][2], a[mb][3]);
            }
            unsigned b[4][2];
            #pragma unroll
            for (int np = 0; np < 2; np++) {
                int krow = k0 + (lane & 15);
                int n0 = wc * 32 + np * 16 + ((lane >> 4) << 3);
                unsigned addr = smem_u32(&sW2[krow * LDT + n0]);
                unsigned r0, r1, r2, r3;
                ldsm_x4_t(addr, r0, r1, r2, r3);
                b[2 * np][0] = r0; b[2 * np][1] = r1;
                b[2 * np + 1][0] = r2; b[2 * np + 1][1] = r3;
            }
            #pragma unroll
            for (int mb = 0; mb < 2; mb++)
                #pragma unroll
                for (int nb = 0; nb < 4; nb++)
                    mma16816(acc[mb][nb][0], acc[mb][nb][1], acc[mb][nb][2], acc[mb][nb][3],
                             a[mb][0], a[mb][1], a[mb][2], a[mb][3], b[nb][0], b[nb][1]);
        }
        #pragma unroll
        for (int mb = 0; mb < 2; mb++) {
            #pragma unroll
            for (int nb = 0; nb < 4; nb++) {
                int col = wc * 32 + nb * 8 + 2 * qlane;
                float bx = sB2[col], by = sB2[col + 1];
                int rlo = rbase + wr * 32 + mb * 16 + rlane;
                float z0 = acc[mb][nb][0] + bx, z1 = acc[mb][nb][1] + by;
                float z2 = acc[mb][nb][2] + bx, z3 = acc[mb][nb][3] + by;
                if (rlo < rend) {
                    *reinterpret_cast<__half2*>(&g_z16[(size_t)rlo * HID + col]) =
                        __floats2half2_rn(z0, z1);
                    ls[2 * nb] += z0; lss[2 * nb] += z0 * z0;
                    ls[2 * nb + 1] += z1; lss[2 * nb + 1] += z1 * z1;
                }
                if (rlo + 8 < rend) {
                    *reinterpret_cast<__half2*>(&g_z16[(size_t)(rlo + 8) * HID + col]) =
                        __floats2half2_rn(z2, z3);
                    ls[2 * nb] += z2; lss[2 * nb] += z2 * z2;
                    ls[2 * nb + 1] += z3; lss[2 * nb + 1] += z3 * z3;
                }
            }
        }
        __syncthreads();
    }

    #pragma unroll
    for (int j = 0; j < 8; j++) {
        #pragma unroll
        for (int o = 4; o < 32; o <<= 1) {
            ls[j]  += __shfl_xor_sync(0xffffffffu, ls[j], o);
            lss[j] += __shfl_xor_sync(0xffffffffu, lss[j], o);
        }
    }
    if (lane < 4) {
        #pragma unroll
        for (int nb = 0; nb < 4; nb++) {
            #pragma unroll
            for (int j = 0; j < 2; j++) {
                int col = wc * 32 + nb * 8 + 2 * lane + j;
                atomicAdd(&stats[col], ls[2 * nb + j]);
                atomicAdd(&stats[HID + col], lss[2 * nb + j]);
            }
        }
    }
}

// ---------------- last layer: BN + relu + pool (reads z16) ------------------
__global__ void bn_pool_kernel(const float* __restrict__ gamma,
                               const float* __restrict__ beta,
                               const float* __restrict__ stats,
                               const int* __restrict__ batch) {
    int i = blockIdx.x * blockDim.x + threadIdx.x;
    const int n4 = N_NODES * HID / 4;
    if (i >= n4) return;
    int n = i >> 5;
    int c0 = (i & 31) * 4;
    float4 z = h16_load4(g_z16 + (size_t)i * 4);
    float za[4] = {z.x, z.y, z.z, z.w};
    float out[4];
    const float invN = 1.0f / (float)N_NODES;
    #pragma unroll
    for (int j = 0; j < 4; j++) {
        int c = c0 + j;
        float mean = stats[c] * invN;
        float var = stats[HID + c] * invN - mean * mean;
        float rstd = rsqrtf(var + BN_EPS);
        float o = gamma[c] * (za[j] - mean) * rstd + beta[c];
        out[j] = fmaxf(o, 0.f);
    }
    int gi = __ldg(&batch[n]);
    red_add_v4(g_pool + (size_t)gi * HID + c0,
               make_float4(out[0], out[1], out[2], out[3]));
}

// ---------------- head: out = relu(g@W1+b1)@W2+b2 ---------------------------
__global__ void head_kernel(const float* __restrict__ w1, const float* __restrict__ b1,
                            const float* __restrict__ w2, const float* __restrict__ b2,
                            float* __restrict__ out) {
    __shared__ float srow[HID];
    __shared__ float st[HID];
    int gi = blockIdx.x;
    int c = threadIdx.x;
    srow[c] = g_pool[(size_t)gi * HID + c];
    __syncthreads();
    float acc = b1[c];
    for (int k = 0; k < HID; k++) acc += srow[k] * w1[k * HID + c];
    st[c] = fmaxf(acc, 0.f);
    __syncthreads();
    if (c < 2) {
        float o = b2[c];
        for (int k = 0; k < HID; k++) o += st[k] * w2[k * 2 + c];
        out[gi * 2 + c] = o;
    }
}

// ---------------- launch (multi-stream captured preamble) --------------------
extern "C" void kernel_launch(void* const* d_in, const int* in_sizes, int n_in,
                              void* d_out, int out_size) {
    const float* x        = (const float*)d_in[0];
    const int*   eidx     = (const int*)d_in[1];
    const float* eattr    = (const float*)d_in[2];
    const int*   batch    = (const int*)d_in[3];
    const float* node_w   = (const float*)d_in[4];
    const float* node_b   = (const float*)d_in[5];
    const float* edge_w   = (const float*)d_in[6];
    const float* edge_b   = (const float*)d_in[7];
    const float* mlp_w1   = (const float*)d_in[8];
    const float* mlp_b1   = (const float*)d_in[9];
    const float* mlp_w2   = (const float*)d_in[10];
    const float* mlp_b2   = (const float*)d_in[11];
    const float* bn_gamma = (const float*)d_in[12];
    const float* bn_beta  = (const float*)d_in[13];
    const float* head_w1  = (const float*)d_in[14];
    const float* head_b1  = (const float*)d_in[15];
    const float* head_w2  = (const float*)d_in[16];
    const float* head_b2  = (const float*)d_in[17];
    float* out = (float*)d_out;

    cudaFuncSetAttribute(mlp_mma_kernel, cudaFuncAttributeMaxDynamicSharedMemorySize,
                         MLP_SMEM_BYTES);

    float* d_stats;
    cudaGetSymbolAddress((void**)&d_stats, g_stats);
    __half* d_w16;
    cudaGetSymbolAddress((void**)&d_w16, g_w16);

    // fork 3 side streams off the capture stream (graph gets parallel branches)
    cudaStream_t s1, s2, s3;
    cudaStreamCreateWithFlags(&s1, cudaStreamNonBlocking);
    cudaStreamCreateWithFlags(&s2, cudaStreamNonBlocking);
    cudaStreamCreateWithFlags(&s3, cudaStreamNonBlocking);
    cudaEvent_t evF, ev1, ev2, ev3;
    cudaEventCreateWithFlags(&evF, cudaEventDisableTiming);
    cudaEventCreateWithFlags(&ev1, cudaEventDisableTiming);
    cudaEventCreateWithFlags(&ev2, cudaEventDisableTiming);
    cudaEventCreateWithFlags(&ev3, cudaEventDisableTiming);

    cudaEventRecord(evF, 0);
    cudaStreamWaitEvent(s1, evF, 0);
    cudaStreamWaitEvent(s2, evF, 0);
    cudaStreamWaitEvent(s3, evF, 0);

    // branch 1: CSR build + edge encoder (critical chain)
    zero_cnt_kernel<<<(N_NODES + 255) / 256, 256, 0, s1>>>();
    csr_count_kernel<<<(N_EDGES + 255) / 256, 256, 0, s1>>>(eidx);
    chunk_sum_kernel<<<NCHUNK / 128, 128, 0, s1>>>();
    chunk_scan_kernel<<<1, NCHUNK, 0, s1>>>();
    chunk_offs_kernel<<<NCHUNK / 128, 128, 0, s1>>>();
    edge_enc_mma_kernel<<<592, 512, 0, s1>>>(eattr, eidx, edge_w, edge_b);
    cudaEventRecord(ev1, s1);

    // branch 2: node encoder
    encoder_kernel<<<512, 256, 0, s2>>>(x, node_w, node_b);
    cudaEventRecord(ev2, s2);

    // branch 3: weight conversion + pool/stats zero
    convert_w_kernel<<<(2 * NLAYERS * HID * HID + 255) / 256, 256, 0, s3>>>(mlp_w1, mlp_w2);
    cudaEventRecord(ev3, s3);

    // join
    cudaStreamWaitEvent(0, ev1, 0);
    cudaStreamWaitEvent(0, ev2, 0);
    cudaStreamWaitEvent(0, ev3, 0);

    const int grid_elem = (N_NODES * HID / 4 + 255) / 256;
    for (int l = 0; l < NLAYERS; l++) {
        agg_kernel<<<4096, 256>>>();
        mlp_mma_kernel<<<148, 512, MLP_SMEM_BYTES>>>(
            d_w16 + (size_t)l * 2 * HID * HID,
            mlp_b1 + (size_t)l * HID,
            mlp_b2 + (size_t)l * HID,
            d_stats + (size_t)l * 2 * HID);
        if (l < NLAYERS - 1) {
            bn_apply_kernel<<<grid_elem, 256>>>(bn_gamma + (size_t)l * HID,
                                                bn_beta + (size_t)l * HID,
                                                d_stats + (size_t)l * 2 * HID);
        }
    }

    bn_pool_kernel<<<grid_elem, 256>>>(
        bn_gamma + (size_t)(NLAYERS - 1) * HID,
        bn_beta + (size_t)(NLAYERS - 1) * HID,
        d_stats + (size_t)(NLAYERS - 1) * 2 * HID, batch);
    head_kernel<<<NGRAPHS, HID>>>(head_w1, head_b1, head_w2, head_b2, out);

    cudaEventDestroy(evF);
    cudaEventDestroy(ev1);
    cudaEventDestroy(ev2);
    cudaEventDestroy(ev3);
    cudaStreamDestroy(s1);
    cudaStreamDestroy(s2);
    cudaStreamDestroy(s3);
}